// round 1
// baseline (speedup 1.0000x reference)
#include <cuda_runtime.h>
#include <cstdint>

#define N_BOX   16384
#define THREADS 1024
#define POST    1000
#define NMS_TH  0.7f
#define MAX_B   8
#define PER_T   (N_BOX / THREADS)   // 16

// Global scratch: sorted-order box SoA per batch (allocation-free rule -> __device__ globals)
__device__ float g_x1[MAX_B * N_BOX];
__device__ float g_y1[MAX_B * N_BOX];
__device__ float g_x2[MAX_B * N_BOX];
__device__ float g_y2[MAX_B * N_BOX];
__device__ float g_ar[MAX_B * N_BOX];

__global__ __launch_bounds__(THREADS, 1)
void proposal_kernel(const float* __restrict__ fg,
                     const float* __restrict__ reg,
                     const float* __restrict__ anc,
                     const int*   __restrict__ p_h,
                     const int*   __restrict__ p_w,
                     float* __restrict__ out, int B)
{
    extern __shared__ unsigned long long s_keys[];        // 131072 B; reused as alive[] after sort
    unsigned char* alive = (unsigned char*)s_keys;

    __shared__ int   s_scan[THREADS];
    __shared__ float s_px1[32], s_py1[32], s_px2[32], s_py2[32], s_pa[32];
    __shared__ int   s_pidx[32], s_cand[32];
    __shared__ int   s_C, s_K, s_cursor, s_last, s_sweepStart;

    const int b   = blockIdx.x;
    const int tid = threadIdx.x;
    const size_t gb = (size_t)b * N_BOX;

    // ---- image dims (robust to int32 or float32 encoding) ----
    int hv = *p_h, wv = *p_w;
    int H = (hv > 0 && hv < 1000000) ? hv : (int)__int_as_float(hv);
    int W = (wv > 0 && wv < 1000000) ? wv : (int)__int_as_float(wv);
    const float maxy = (float)H - 1.0f;
    const float maxx = (float)W - 1.0f;

    // ---- output pointers (tuple concatenated as f32) ----
    float* obox = out;                              // [B,1000,4]
    float* oidx = out + (size_t)B * POST * 4;       // [B,1000]
    float* oval = oidx + (size_t)B * POST;          // [B,1000]

    // ---- phase 1: build sort keys (score desc, index asc via single u64) ----
    const float* fgb = fg + gb;
    for (int j = tid; j < N_BOX; j += THREADS) {
        unsigned u   = __float_as_uint(fgb[j]);
        unsigned asc = u ^ ((u >> 31) ? 0xFFFFFFFFu : 0x80000000u); // ascending order of float
        unsigned dsc = ~asc;                                        // descending
        s_keys[j] = ((unsigned long long)dsc << 32) | (unsigned)j;
    }
    // init outputs for this batch
    for (int r = tid; r < POST; r += THREADS) {
        size_t o = ((size_t)b * POST + r) * 4;
        obox[o + 0] = 0.f; obox[o + 1] = 0.f; obox[o + 2] = 0.f; obox[o + 3] = 0.f;
        oidx[(size_t)b * POST + r] = -1.0f;
        oval[(size_t)b * POST + r] = 0.0f;
    }
    __syncthreads();

    // ---- phase 2: bitonic sort (ascending u64 == score desc, idx asc) ----
    for (int k = 2; k <= N_BOX; k <<= 1) {
        for (int jj = k >> 1; jj > 0; jj >>= 1) {
            for (int i = tid; i < N_BOX; i += THREADS) {
                int ixj = i ^ jj;
                if (ixj > i) {
                    unsigned long long a = s_keys[i], c = s_keys[ixj];
                    bool up = ((i & k) == 0);
                    if ((a > c) == up) { s_keys[i] = c; s_keys[ixj] = a; }
                }
            }
            __syncthreads();
        }
    }

    // ---- phase 3: gather in sorted order, decode + clip boxes -> global SoA ----
    const float4* anc4 = (const float4*)anc + gb;
    const float4* reg4 = (const float4*)reg + gb;
    for (int j = tid; j < N_BOX; j += THREADS) {
        int i = (int)(unsigned)(s_keys[j] & 0xFFFFFFFFull);
        float4 A = anc4[i];   // sx, sy, sw, sh
        float4 R = reg4[i];   // ox, oy, ow, oh
        float cx = A.z * R.x + A.x;
        float cy = A.w * R.y + A.y;
        float w  = A.z * expf(R.z);
        float h  = A.w * expf(R.w);
        float x1 = fminf(fmaxf(cx - w * 0.5f, 0.f), maxx);
        float x2 = fminf(fmaxf(cx + w * 0.5f, 0.f), maxx);
        float y1 = fminf(fmaxf(cy - h * 0.5f, 0.f), maxy);
        float y2 = fminf(fmaxf(cy + h * 0.5f, 0.f), maxy);
        g_x1[gb + j] = x1; g_y1[gb + j] = y1;
        g_x2[gb + j] = x2; g_y2[gb + j] = y2;
        g_ar[gb + j] = (x2 - x1) * (y2 - y1);
    }
    __syncthreads();   // keys dead; region becomes alive[]

    for (int j = tid; j < N_BOX; j += THREADS) alive[j] = 1;
    if (tid == 0) s_cursor = 0;
    __syncthreads();

    // ---- phase 4: chunked multi-pivot greedy NMS ----
    for (;;) {
        if (tid < 32) {
            const int lane = tid;
            // gather next <=32 alive candidate indices from cursor
            int cnt = 0, cur = s_cursor;
            while (cnt < 32 && cur < N_BOX) {
                int j = cur + lane;
                bool a = (j < N_BOX) && alive[j];
                unsigned m = __ballot_sync(0xffffffffu, a);
                int avail = __popc(m);
                int r = __popc(m & ((1u << lane) - 1u));
                int need = 32 - cnt;
                if (a && r < need) s_cand[cnt + r] = j;
                if (avail >= need) {
                    if (a && r == need - 1) s_last = j;
                    cnt = 32;
                } else {
                    cnt += avail; cur += 32;
                }
            }
            __syncwarp();
            const int C = cnt;

            // load candidate boxes
            float x1 = 0.f, y1 = 0.f, x2 = 0.f, y2 = 0.f, ar = 0.f;
            int ci = -1;
            bool al = (lane < C);
            if (al) {
                ci = s_cand[lane];
                x1 = g_x1[gb + ci]; y1 = g_y1[gb + ci];
                x2 = g_x2[gb + ci]; y2 = g_y2[gb + ci];
                ar = g_ar[gb + ci];
            }
            // in-warp sequential greedy among the chunk (matches reference order exactly)
            for (int p = 0; p < C; p++) {
                unsigned mask = __ballot_sync(0xffffffffu, al);
                if (!((mask >> p) & 1u)) continue;
                float bx1 = __shfl_sync(0xffffffffu, x1, p);
                float by1 = __shfl_sync(0xffffffffu, y1, p);
                float bx2 = __shfl_sync(0xffffffffu, x2, p);
                float by2 = __shfl_sync(0xffffffffu, y2, p);
                float ba  = __shfl_sync(0xffffffffu, ar, p);
                if (al && lane > p) {
                    float iw = fminf(x2, bx2) - fmaxf(x1, bx1);
                    float ih = fminf(y2, by2) - fmaxf(y1, by1);
                    float inter = fmaxf(iw, 0.f) * fmaxf(ih, 0.f);
                    float iou = inter / (ba + ar - inter + 1e-9f);
                    if (iou > NMS_TH) al = false;
                }
            }
            unsigned fm = __ballot_sync(0xffffffffu, al);
            if (lane < C) {
                alive[ci] = al ? (unsigned char)1 : (unsigned char)0;
                if (al) {
                    int r = __popc(fm & ((1u << lane) - 1u));
                    s_px1[r] = x1; s_py1[r] = y1; s_px2[r] = x2; s_py2[r] = y2;
                    s_pa[r]  = ar; s_pidx[r] = ci;
                }
            }
            if (lane == 0) {
                s_K = __popc(fm);
                s_C = C;
                s_sweepStart = (C > 0) ? (s_cand[0] + 1) : N_BOX;
                s_cursor = (C == 32) ? (s_last + 1) : N_BOX;
            }
        }
        __syncthreads();
        if (s_C == 0) break;

        const int K = s_K;
        if (K > 0) {
            for (int j = s_sweepStart + tid; j < N_BOX; j += THREADS) {
                if (!alive[j]) continue;
                float x1 = g_x1[gb + j], x2 = g_x2[gb + j];
                float y1 = g_y1[gb + j], y2 = g_y2[gb + j];
                float a  = g_ar[gb + j];
                for (int p = 0; p < K; p++) {
                    if (s_pidx[p] >= j) break;   // pivots ascending; only earlier boxes suppress
                    float iw = fminf(x2, s_px2[p]) - fmaxf(x1, s_px1[p]);
                    if (iw <= 0.f) continue;
                    float ih = fminf(y2, s_py2[p]) - fmaxf(y1, s_py1[p]);
                    if (ih <= 0.f) continue;
                    float inter = iw * ih;
                    float iou = inter / (s_pa[p] + a - inter + 1e-9f);
                    if (iou > NMS_TH) { alive[j] = 0; break; }
                }
            }
        }
        __syncthreads();
    }

    // ---- phase 5: prefix-scan keep flags, emit top-1000 ----
    const int base = tid * PER_T;
    int cnt = 0;
    #pragma unroll
    for (int k = 0; k < PER_T; k++) cnt += alive[base + k];

    int v = cnt;
    s_scan[tid] = v;
    __syncthreads();
    for (int off = 1; off < THREADS; off <<= 1) {
        int t = (tid >= off) ? s_scan[tid - off] : 0;
        __syncthreads();
        v += t;
        s_scan[tid] = v;
        __syncthreads();
    }
    int r = v - cnt;   // exclusive prefix = output rank of first kept box in my segment

    #pragma unroll
    for (int k = 0; k < PER_T; k++) {
        int j = base + k;
        if (alive[j]) {
            if (r < POST) {
                size_t o = ((size_t)b * POST + r) * 4;
                obox[o + 0] = g_x1[gb + j];
                obox[o + 1] = g_y1[gb + j];
                obox[o + 2] = g_x2[gb + j];
                obox[o + 3] = g_y2[gb + j];
                oidx[(size_t)b * POST + r] = (float)j;
                oval[(size_t)b * POST + r] = 1.0f;
            }
            r++;
        }
    }
}

extern "C" void kernel_launch(void* const* d_in, const int* in_sizes, int n_in,
                              void* d_out, int out_size)
{
    const float* fg  = (const float*)d_in[0];
    const float* reg = (const float*)d_in[1];
    const float* anc = (const float*)d_in[2];
    const int*   ph  = (const int*)d_in[3];
    const int*   pw  = (const int*)d_in[4];

    int B = in_sizes[0] / N_BOX;
    if (B < 1) B = 1;
    if (B > MAX_B) B = MAX_B;

    cudaFuncSetAttribute(proposal_kernel,
                         cudaFuncAttributeMaxDynamicSharedMemorySize,
                         N_BOX * (int)sizeof(unsigned long long));

    proposal_kernel<<<B, THREADS, N_BOX * sizeof(unsigned long long)>>>(
        fg, reg, anc, ph, pw, (float*)d_out, B);
}

// round 2
// speedup vs baseline: 9.8973x; 9.8973x over previous
#include <cuda_runtime.h>
#include <cstdint>

#define N_BOX   16384
#define THREADS 1024
#define POST    1000
#define NMS_TH  0.7f
#define MAX_B   8
#define NW      256            // 64-bit words per mask row (16384/64)

// Global scratch (allocation-free rule -> __device__ globals)
__device__ float4 g_box [MAX_B * N_BOX];                 // sorted-order clipped boxes (x1,y1,x2,y2)
__device__ float  g_area[MAX_B * N_BOX];                 // areas
__device__ unsigned long long g_mask[(size_t)MAX_B * N_BOX * NW];   // 268 MB suppression bitmask

// ------------------------------------------------------------------
// Kernel 1: per-batch stable sort by score (desc) + decode/clip boxes
// ------------------------------------------------------------------
__global__ __launch_bounds__(THREADS, 1)
void sort_decode_kernel(const float* __restrict__ fg,
                        const float* __restrict__ reg,
                        const float* __restrict__ anc,
                        const int*   __restrict__ p_h,
                        const int*   __restrict__ p_w)
{
    extern __shared__ unsigned long long s_keys[];   // 131072 B
    const int b   = blockIdx.x;
    const int tid = threadIdx.x;
    const size_t gb = (size_t)b * N_BOX;

    int hv = *p_h, wv = *p_w;
    int H = (hv > 0 && hv < 1000000) ? hv : (int)__int_as_float(hv);
    int W = (wv > 0 && wv < 1000000) ? wv : (int)__int_as_float(wv);
    const float maxy = (float)H - 1.0f;
    const float maxx = (float)W - 1.0f;

    // keys: (score desc, index asc) packed into one u64, ascending sort
    const float* fgb = fg + gb;
    for (int j = tid; j < N_BOX; j += THREADS) {
        unsigned u   = __float_as_uint(fgb[j]);
        unsigned asc = u ^ ((u >> 31) ? 0xFFFFFFFFu : 0x80000000u);
        unsigned dsc = ~asc;
        s_keys[j] = ((unsigned long long)dsc << 32) | (unsigned)j;
    }
    __syncthreads();

    // bitonic sort (ascending)
    for (int k = 2; k <= N_BOX; k <<= 1) {
        for (int jj = k >> 1; jj > 0; jj >>= 1) {
            for (int i = tid; i < N_BOX; i += THREADS) {
                int ixj = i ^ jj;
                if (ixj > i) {
                    unsigned long long a = s_keys[i], c = s_keys[ixj];
                    bool up = ((i & k) == 0);
                    if ((a > c) == up) { s_keys[i] = c; s_keys[ixj] = a; }
                }
            }
            __syncthreads();
        }
    }

    // gather + decode + clip into sorted-order SoA
    const float4* anc4 = (const float4*)anc + gb;
    const float4* reg4 = (const float4*)reg + gb;
    for (int j = tid; j < N_BOX; j += THREADS) {
        int i = (int)(unsigned)(s_keys[j] & 0xFFFFFFFFull);
        float4 A = anc4[i];   // sx, sy, sw, sh
        float4 R = reg4[i];   // ox, oy, ow, oh
        float cx = A.z * R.x + A.x;
        float cy = A.w * R.y + A.y;
        float w  = A.z * expf(R.z);
        float h  = A.w * expf(R.w);
        float x1 = fminf(fmaxf(cx - w * 0.5f, 0.f), maxx);
        float x2 = fminf(fmaxf(cx + w * 0.5f, 0.f), maxx);
        float y1 = fminf(fmaxf(cy - h * 0.5f, 0.f), maxy);
        float y2 = fminf(fmaxf(cy + h * 0.5f, 0.f), maxy);
        g_box [gb + j] = make_float4(x1, y1, x2, y2);
        g_area[gb + j] = (x2 - x1) * (y2 - y1);
    }
}

// ------------------------------------------------------------------
// Kernel 2: suppression bitmask generation (fully parallel, all SMs)
// block = 256 rows x 64 cols tile; writes one u64 word per row
// ------------------------------------------------------------------
__global__ __launch_bounds__(256)
void maskgen_kernel()
{
    const int rt = blockIdx.x;          // row tile (256 rows)
    const int ct = blockIdx.y;          // col tile (64 cols) == word index
    const int b  = blockIdx.z;
    const int rowbase = rt << 8;
    const int colbase = ct << 6;
    if (colbase < rowbase) return;      // word never read by resolution

    __shared__ float4 sb[64];
    __shared__ float  sa[64];
    const int tid = threadIdx.x;
    const size_t gb = (size_t)b * N_BOX;

    if (tid < 64) {
        sb[tid] = g_box [gb + colbase + tid];
        sa[tid] = g_area[gb + colbase + tid];
    }
    __syncthreads();

    const int i = rowbase + tid;
    float4 rb = g_box [gb + i];
    float  ra = g_area[gb + i];

    unsigned long long bits = 0;
    int jstart = i + 1 - colbase;
    if (jstart < 0) jstart = 0;
    for (int cc = jstart; cc < 64; cc++) {
        float4 cb = sb[cc];
        float iw = fminf(rb.z, cb.z) - fmaxf(rb.x, cb.x);
        float ih = fminf(rb.w, cb.w) - fmaxf(rb.y, cb.y);
        if (iw > 0.f && ih > 0.f) {
            float inter = iw * ih;
            float iou = inter / (ra + sa[cc] - inter + 1e-9f);
            if (iou > NMS_TH) bits |= 1ull << cc;
        }
    }
    g_mask[(gb + i) * NW + ct] = bits;
}

// ------------------------------------------------------------------
// Kernel 3: sequential greedy resolution on precomputed mask + emit
// one block per batch, 1024 threads
// ------------------------------------------------------------------
__global__ __launch_bounds__(THREADS, 1)
void resolve_kernel(float* __restrict__ out, int B)
{
    __shared__ unsigned long long remv [NW];   // running suppressed bitmap
    __shared__ unsigned long long keepw[NW];   // kept bits per word
    __shared__ unsigned long long s_diag[64];
    __shared__ unsigned long long s_kept;
    __shared__ int s_scan[NW];

    const int b   = blockIdx.x;
    const int tid = threadIdx.x;
    const size_t gb = (size_t)b * N_BOX;

    float* obox = out;                              // [B,1000,4]
    float* oidx = out + (size_t)B * POST * 4;       // [B,1000]
    float* oval = oidx + (size_t)B * POST;          // [B,1000]

    // init outputs
    for (int r = tid; r < POST; r += THREADS) {
        size_t o = ((size_t)b * POST + r) * 4;
        obox[o + 0] = 0.f; obox[o + 1] = 0.f; obox[o + 2] = 0.f; obox[o + 3] = 0.f;
        oidx[(size_t)b * POST + r] = -1.0f;
        oval[(size_t)b * POST + r] = 0.0f;
    }
    if (tid < NW) remv[tid] = 0ull;
    __syncthreads();

    for (int c = 0; c < NW; c++) {
        const int base = c << 6;
        // preload diagonal words for this chunk
        if (tid < 64) s_diag[tid] = g_mask[(gb + base + tid) * NW + c];
        __syncthreads();

        // serial in-chunk greedy (64 steps on precomputed edges)
        if (tid == 0) {
            unsigned long long w = remv[c], kept = 0;
            #pragma unroll
            for (int r = 0; r < 64; r++) {
                unsigned long long bit = 1ull << r;
                if (!(w & bit)) { w |= s_diag[r]; kept |= bit; }
            }
            keepw[c] = kept;
            s_kept   = kept;
        }
        __syncthreads();

        // OR kept rows' tail words into remv (parallel, coalesced in k)
        const unsigned long long kb = s_kept;
        const int nwords = NW - 1 - c;
        if (kb && nwords > 0) {
            const int nunits = nwords * 4;   // 4 groups of 16 rows per word
            for (int u = tid; u < nunits; u += THREADS) {
                int k = c + 1 + (u % nwords);        // consecutive lanes -> consecutive k
                int g = (u / nwords) * 16;
                unsigned t = (unsigned)((kb >> g) & 0xFFFFull);
                if (!t) continue;
                unsigned long long acc = 0;
                const unsigned long long* mp = &g_mask[(gb + base + g) * NW + k];
                #pragma unroll
                for (int rr = 0; rr < 16; rr++)
                    if ((t >> rr) & 1u) acc |= mp[(size_t)rr * NW];
                if (acc) atomicOr(&remv[k], acc);
            }
        }
        __syncthreads();
    }

    // ---- emit: prefix scan of popcounts, write top-1000 kept ----
    if (tid < NW) s_scan[tid] = __popcll(keepw[tid]);
    __syncthreads();
    for (int off = 1; off < NW; off <<= 1) {
        int v = 0;
        if (tid < NW) { v = s_scan[tid]; if (tid >= off) v += s_scan[tid - off]; }
        __syncthreads();
        if (tid < NW) s_scan[tid] = v;
        __syncthreads();
    }
    if (tid < NW) {
        unsigned long long kw = keepw[tid];
        int r = s_scan[tid] - __popcll(kw);      // exclusive prefix = output rank
        const int base = tid << 6;
        while (kw && r < POST) {
            int rr = __ffsll((long long)kw) - 1;
            kw &= kw - 1;
            int j = base + rr;
            float4 bx = g_box[gb + j];
            size_t o = ((size_t)b * POST + r) * 4;
            obox[o + 0] = bx.x; obox[o + 1] = bx.y;
            obox[o + 2] = bx.z; obox[o + 3] = bx.w;
            oidx[(size_t)b * POST + r] = (float)j;
            oval[(size_t)b * POST + r] = 1.0f;
            r++;
        }
    }
}

// ------------------------------------------------------------------
extern "C" void kernel_launch(void* const* d_in, const int* in_sizes, int n_in,
                              void* d_out, int out_size)
{
    const float* fg  = (const float*)d_in[0];
    const float* reg = (const float*)d_in[1];
    const float* anc = (const float*)d_in[2];
    const int*   ph  = (const int*)d_in[3];
    const int*   pw  = (const int*)d_in[4];

    int B = in_sizes[0] / N_BOX;
    if (B < 1) B = 1;
    if (B > MAX_B) B = MAX_B;

    cudaFuncSetAttribute(sort_decode_kernel,
                         cudaFuncAttributeMaxDynamicSharedMemorySize,
                         N_BOX * (int)sizeof(unsigned long long));

    sort_decode_kernel<<<B, THREADS, N_BOX * sizeof(unsigned long long)>>>(fg, reg, anc, ph, pw);
    maskgen_kernel<<<dim3(N_BOX / 256, NW, B), 256>>>();
    resolve_kernel<<<B, THREADS>>>((float*)d_out, B);
}

// round 3
// speedup vs baseline: 10.0990x; 1.0204x over previous
#include <cuda_runtime.h>
#include <cstdint>

typedef unsigned long long u64;

#define N_BOX   16384
#define TSORT   1024
#define POST    1000
#define NMS_TH  0.7f
#define MAX_B   8
#define NW      256            // 64-bit words per mask row

// Global scratch (allocation-free rule -> __device__ globals)
__device__ float4 g_box [MAX_B * N_BOX];
__device__ float  g_area[MAX_B * N_BOX];
__device__ u64    g_mask[(size_t)MAX_B * N_BOX * NW];   // sparse: only nonzero words valid (gated by g_sum)
__device__ u64    g_diag[MAX_B * N_BOX];                // always-written diagonal word per row
__device__ u64    g_sum [MAX_B * N_BOX * 4];            // per-row 256-bit summary of nonzero tail words

__device__ __forceinline__ int physi(int i) { return i + (i >> 4); }   // bank-skew map

// ------------------------------------------------------------------
// Kernel 0: zero the summary bitmaps (must precede maskgen)
// ------------------------------------------------------------------
__global__ void zero_sum_kernel()
{
    size_t n = (size_t)MAX_B * N_BOX * 4;
    for (size_t i = (size_t)blockIdx.x * blockDim.x + threadIdx.x; i < n;
         i += (size_t)gridDim.x * blockDim.x)
        g_sum[i] = 0ull;
}

// ------------------------------------------------------------------
// Kernel 1: per-batch stable sort (score desc, idx asc) + decode/clip
// bitonic with in-register jj<=8 stages
// ------------------------------------------------------------------
template<int JJ>
__device__ __forceinline__ void reg_stage(u64 v[16], int base, int k)
{
    #pragma unroll
    for (int l = 0; l < 16; l++) if ((l & JJ) == 0) {
        const int p = l | JJ;
        bool up = (((base + l) & k) == 0);
        u64 a = v[l], c = v[p];
        if ((a > c) == up) { v[l] = c; v[p] = a; }
    }
}

__global__ __launch_bounds__(TSORT, 1)
void sort_decode_kernel(const float* __restrict__ fg,
                        const float* __restrict__ reg,
                        const float* __restrict__ anc,
                        const int*   __restrict__ p_h,
                        const int*   __restrict__ p_w)
{
    extern __shared__ u64 sk[];   // physi-mapped, 17408 u64
    const int b   = blockIdx.x;
    const int tid = threadIdx.x;
    const size_t gb = (size_t)b * N_BOX;

    int hv = *p_h, wv = *p_w;
    int H = (hv > 0 && hv < 1000000) ? hv : (int)__int_as_float(hv);
    int W = (wv > 0 && wv < 1000000) ? wv : (int)__int_as_float(wv);
    const float maxy = (float)H - 1.0f;
    const float maxx = (float)W - 1.0f;

    // build keys
    const float* fgb = fg + gb;
    for (int j = tid; j < N_BOX; j += TSORT) {
        unsigned u   = __float_as_uint(fgb[j]);
        unsigned asc = u ^ ((u >> 31) ? 0xFFFFFFFFu : 0x80000000u);
        sk[physi(j)] = ((u64)(~asc) << 32) | (unsigned)j;
    }
    __syncthreads();

    // k = 2..16 entirely in registers
    const int base = tid * 16;
    u64 v[16];
    #pragma unroll
    for (int l = 0; l < 16; l++) v[l] = sk[physi(base + l)];
    reg_stage<1>(v, base, 2);
    reg_stage<2>(v, base, 4);  reg_stage<1>(v, base, 4);
    reg_stage<4>(v, base, 8);  reg_stage<2>(v, base, 8);  reg_stage<1>(v, base, 8);
    reg_stage<8>(v, base, 16); reg_stage<4>(v, base, 16); reg_stage<2>(v, base, 16); reg_stage<1>(v, base, 16);
    #pragma unroll
    for (int l = 0; l < 16; l++) sk[physi(base + l)] = v[l];
    __syncthreads();

    // k = 32..16384: smem stages jj>=16, then register stages jj<=8
    for (int k = 32; k <= N_BOX; k <<= 1) {
        for (int jj = k >> 1; jj >= 16; jj >>= 1) {
            for (int s = tid; s < N_BOX / 2; s += TSORT) {
                int i  = ((s & ~(jj - 1)) << 1) | (s & (jj - 1));
                int j2 = i | jj;
                bool up = ((i & k) == 0);
                int pi = physi(i), pj = physi(j2);
                u64 a = sk[pi], c = sk[pj];
                if ((a > c) == up) { sk[pi] = c; sk[pj] = a; }
            }
            __syncthreads();
        }
        #pragma unroll
        for (int l = 0; l < 16; l++) v[l] = sk[physi(base + l)];
        reg_stage<8>(v, base, k); reg_stage<4>(v, base, k);
        reg_stage<2>(v, base, k); reg_stage<1>(v, base, k);
        #pragma unroll
        for (int l = 0; l < 16; l++) sk[physi(base + l)] = v[l];
        __syncthreads();
    }

    // gather + decode + clip into sorted-order SoA
    const float4* anc4 = (const float4*)anc + gb;
    const float4* reg4 = (const float4*)reg + gb;
    for (int j = tid; j < N_BOX; j += TSORT) {
        int i = (int)(unsigned)(sk[physi(j)] & 0xFFFFFFFFull);
        float4 A = anc4[i];
        float4 R = reg4[i];
        float cx = A.z * R.x + A.x;
        float cy = A.w * R.y + A.y;
        float w  = A.z * expf(R.z);
        float h  = A.w * expf(R.w);
        float x1 = fminf(fmaxf(cx - w * 0.5f, 0.f), maxx);
        float x2 = fminf(fmaxf(cx + w * 0.5f, 0.f), maxx);
        float y1 = fminf(fmaxf(cy - h * 0.5f, 0.f), maxy);
        float y2 = fminf(fmaxf(cy + h * 0.5f, 0.f), maxy);
        g_box [gb + j] = make_float4(x1, y1, x2, y2);
        g_area[gb + j] = (x2 - x1) * (y2 - y1);
    }
}

// ------------------------------------------------------------------
// Kernel 2: sparse suppression-bitmask generation
// block = 256 rows x 256 cols (4 words); bracket test avoids most divisions
// ------------------------------------------------------------------
__global__ __launch_bounds__(256)
void maskgen_kernel()
{
    const int rt = blockIdx.x;          // 256-row tile
    const int cg = blockIdx.y;          // 256-col tile
    const int b  = blockIdx.z;
    if (cg < rt) return;                // strictly below diagonal

    const int rowbase = rt << 8;
    const int colbase = cg << 8;

    __shared__ float4 s_cb[256];
    __shared__ float  s_ca[256];
    const int tid = threadIdx.x;
    const size_t gb = (size_t)b * N_BOX;

    s_cb[tid] = g_box [gb + colbase + tid];
    s_ca[tid] = g_area[gb + colbase + tid];
    __syncthreads();

    const int i = rowbase + tid;
    const float4 rb = g_box [gb + i];
    const float  ra = g_area[gb + i];
    const int myword = i >> 6;

    #pragma unroll
    for (int w = 0; w < 4; w++) {
        const int ct  = (cg << 2) + w;
        const int cwb = ct << 6;
        int jstart = i + 1 - cwb;
        if (jstart < 0) jstart = 0;
        u64 bits = 0;
        for (int cc = jstart; cc < 64; cc++) {
            float4 cb = s_cb[(w << 6) + cc];
            float iw = fminf(rb.z, cb.z) - fmaxf(rb.x, cb.x);
            float ih = fminf(rb.w, cb.w) - fmaxf(rb.y, cb.y);
            if (iw > 0.f && ih > 0.f) {
                float inter = iw * ih;
                float denom = ra + s_ca[(w << 6) + cc] - inter + 1e-9f;
                // bracket: +/-2% margin >> fp rounding; exact division only inside
                if (inter > 0.714f * denom) {
                    bits |= 1ull << cc;
                } else if (inter >= 0.686f * denom) {
                    float iou = inter / denom;
                    if (iou > NMS_TH) bits |= 1ull << cc;
                }
            }
        }
        if (ct == myword) {
            g_diag[gb + i] = bits;
        } else if (bits) {
            g_mask[(gb + i) * NW + ct] = bits;
            atomicOr(&g_sum[((gb + i) << 2) + (ct >> 6)], 1ull << (ct & 63));
        }
    }
}

// ------------------------------------------------------------------
// Kernel 3: sparse sequential greedy resolution + emit
// one block per batch, 256 threads, double-buffered prefetch
// ------------------------------------------------------------------
__global__ __launch_bounds__(NW, 1)
void resolve_kernel(float* __restrict__ out, int B)
{
    __shared__ u64 remv [NW];
    __shared__ u64 keepw[NW];
    __shared__ u64 sdiag[2][64];
    __shared__ u64 ssum [2][256];      // [row r*4 + word j]
    __shared__ u64 s_kept;
    __shared__ int s_scan[NW];

    const int b   = blockIdx.x;
    const int tid = threadIdx.x;
    const size_t gb = (size_t)b * N_BOX;

    float* obox = out;
    float* oidx = out + (size_t)B * POST * 4;
    float* oval = oidx + (size_t)B * POST;

    for (int r = tid; r < POST; r += NW) {
        size_t o = ((size_t)b * POST + r) * 4;
        obox[o + 0] = 0.f; obox[o + 1] = 0.f; obox[o + 2] = 0.f; obox[o + 3] = 0.f;
        oidx[(size_t)b * POST + r] = -1.0f;
        oval[(size_t)b * POST + r] = 0.0f;
    }
    remv[tid] = 0ull;

    // prefetch chunk 0
    if (tid < 64) sdiag[0][tid] = g_diag[gb + tid];
    ssum[0][tid] = g_sum[(gb << 2) + tid];
    __syncthreads();

    for (int c = 0; c < NW; c++) {
        const int buf = c & 1, nb = buf ^ 1;

        // prefetch chunk c+1 (overlaps serial step below)
        if (c + 1 < NW) {
            const int nbase = (c + 1) << 6;
            if (tid < 64) sdiag[nb][tid] = g_diag[gb + nbase + tid];
            ssum[nb][tid] = g_sum[((gb + nbase) << 2) + tid];
        }

        // serial greedy within the chunk (precomputed edges)
        if (tid == 0) {
            u64 kept = 0;
            u64 und  = ~remv[c];
            while (und) {
                int r = __ffsll((long long)und) - 1;
                kept |= 1ull << r;
                u64 d = sdiag[buf][r];
                und &= ~(d | (1ull << r));
            }
            keepw[c] = kept;
            s_kept   = kept;
        }
        __syncthreads();

        // sparse sweep: kept rows OR their (few) nonzero tail words into remv
        const u64 kb = s_kept;
        if (tid < 64 && ((kb >> tid) & 1ull)) {
            const int row = (c << 6) + tid;
            const u64* sp = &ssum[buf][tid << 2];
            #pragma unroll
            for (int j = 0; j < 4; j++) {
                u64 s = sp[j];
                while (s) {
                    int k = (j << 6) + __ffsll((long long)s) - 1;
                    s &= s - 1;
                    atomicOr(&remv[k], g_mask[(gb + row) * NW + k]);
                }
            }
        }
        __syncthreads();
    }

    // emit: prefix scan of popcounts, write top-1000 kept
    s_scan[tid] = __popcll(keepw[tid]);
    __syncthreads();
    for (int off = 1; off < NW; off <<= 1) {
        int vv = s_scan[tid];
        if (tid >= off) vv += s_scan[tid - off];
        __syncthreads();
        s_scan[tid] = vv;
        __syncthreads();
    }
    {
        u64 kw = keepw[tid];
        int r = s_scan[tid] - __popcll(kw);
        const int base = tid << 6;
        while (kw && r < POST) {
            int rr = __ffsll((long long)kw) - 1;
            kw &= kw - 1;
            int j = base + rr;
            float4 bx = g_box[gb + j];
            size_t o = ((size_t)b * POST + r) * 4;
            obox[o + 0] = bx.x; obox[o + 1] = bx.y;
            obox[o + 2] = bx.z; obox[o + 3] = bx.w;
            oidx[(size_t)b * POST + r] = (float)j;
            oval[(size_t)b * POST + r] = 1.0f;
            r++;
        }
    }
}

// ------------------------------------------------------------------
extern "C" void kernel_launch(void* const* d_in, const int* in_sizes, int n_in,
                              void* d_out, int out_size)
{
    const float* fg  = (const float*)d_in[0];
    const float* reg = (const float*)d_in[1];
    const float* anc = (const float*)d_in[2];
    const int*   ph  = (const int*)d_in[3];
    const int*   pw  = (const int*)d_in[4];

    int B = in_sizes[0] / N_BOX;
    if (B < 1) B = 1;
    if (B > MAX_B) B = MAX_B;

    const int SORT_SMEM = (N_BOX + N_BOX / 16) * (int)sizeof(u64);   // 139264
    cudaFuncSetAttribute(sort_decode_kernel,
                         cudaFuncAttributeMaxDynamicSharedMemorySize, SORT_SMEM);

    zero_sum_kernel<<<512, 256>>>();
    sort_decode_kernel<<<B, TSORT, SORT_SMEM>>>(fg, reg, anc, ph, pw);
    maskgen_kernel<<<dim3(N_BOX / 256, N_BOX / 256, B), 256>>>();
    resolve_kernel<<<B, NW>>>((float*)d_out, B);
}

// round 4
// speedup vs baseline: 10.2221x; 1.0122x over previous
#include <cuda_runtime.h>
#include <cstdint>

typedef unsigned long long u64;

#define N_BOX   16384
#define TSORT   1024
#define POST    1000
#define NMS_TH  0.7f
#define MAX_B   8
#define NW      256            // 64-bit words per mask row

// Global scratch (allocation-free rule -> __device__ globals)
__device__ float4 g_box [MAX_B * N_BOX];
__device__ float  g_area[MAX_B * N_BOX];
__device__ u64    g_mask[(size_t)MAX_B * N_BOX * NW];   // sparse: nonzero words only (gated by g_sum)
__device__ u64    g_diag[MAX_B * N_BOX];                // diagonal word per row (dense)
__device__ u64    g_sum [MAX_B * N_BOX * 4];            // per-row 256-bit summary of nonzero tail words

__device__ __forceinline__ int physi(int i) { return i + (i >> 4); }   // bank-skew map

// ------------------------------------------------------------------
// Kernel 0: zero the summary bitmaps
// ------------------------------------------------------------------
__global__ void zero_sum_kernel()
{
    size_t n = (size_t)MAX_B * N_BOX * 4;
    for (size_t i = (size_t)blockIdx.x * blockDim.x + threadIdx.x; i < n;
         i += (size_t)gridDim.x * blockDim.x)
        g_sum[i] = 0ull;
}

// ------------------------------------------------------------------
// Kernel 1: per-batch stable sort (score desc, idx asc) + decode/clip
// ------------------------------------------------------------------
template<int JJ>
__device__ __forceinline__ void reg_stage(u64 v[16], int base, int k)
{
    #pragma unroll
    for (int l = 0; l < 16; l++) if ((l & JJ) == 0) {
        const int p = l | JJ;
        bool up = (((base + l) & k) == 0);
        u64 a = v[l], c = v[p];
        if ((a > c) == up) { v[l] = c; v[p] = a; }
    }
}

__global__ __launch_bounds__(TSORT, 1)
void sort_decode_kernel(const float* __restrict__ fg,
                        const float* __restrict__ reg,
                        const float* __restrict__ anc,
                        const int*   __restrict__ p_h,
                        const int*   __restrict__ p_w)
{
    extern __shared__ u64 sk[];
    const int b   = blockIdx.x;
    const int tid = threadIdx.x;
    const size_t gb = (size_t)b * N_BOX;

    int hv = *p_h, wv = *p_w;
    int H = (hv > 0 && hv < 1000000) ? hv : (int)__int_as_float(hv);
    int W = (wv > 0 && wv < 1000000) ? wv : (int)__int_as_float(wv);
    const float maxy = (float)H - 1.0f;
    const float maxx = (float)W - 1.0f;

    const float* fgb = fg + gb;
    for (int j = tid; j < N_BOX; j += TSORT) {
        unsigned u   = __float_as_uint(fgb[j]);
        unsigned asc = u ^ ((u >> 31) ? 0xFFFFFFFFu : 0x80000000u);
        sk[physi(j)] = ((u64)(~asc) << 32) | (unsigned)j;
    }
    __syncthreads();

    const int base = tid * 16;
    u64 v[16];
    #pragma unroll
    for (int l = 0; l < 16; l++) v[l] = sk[physi(base + l)];
    reg_stage<1>(v, base, 2);
    reg_stage<2>(v, base, 4);  reg_stage<1>(v, base, 4);
    reg_stage<4>(v, base, 8);  reg_stage<2>(v, base, 8);  reg_stage<1>(v, base, 8);
    reg_stage<8>(v, base, 16); reg_stage<4>(v, base, 16); reg_stage<2>(v, base, 16); reg_stage<1>(v, base, 16);
    #pragma unroll
    for (int l = 0; l < 16; l++) sk[physi(base + l)] = v[l];
    __syncthreads();

    for (int k = 32; k <= N_BOX; k <<= 1) {
        for (int jj = k >> 1; jj >= 16; jj >>= 1) {
            for (int s = tid; s < N_BOX / 2; s += TSORT) {
                int i  = ((s & ~(jj - 1)) << 1) | (s & (jj - 1));
                int j2 = i | jj;
                bool up = ((i & k) == 0);
                int pi = physi(i), pj = physi(j2);
                u64 a = sk[pi], c = sk[pj];
                if ((a > c) == up) { sk[pi] = c; sk[pj] = a; }
            }
            __syncthreads();
        }
        #pragma unroll
        for (int l = 0; l < 16; l++) v[l] = sk[physi(base + l)];
        reg_stage<8>(v, base, k); reg_stage<4>(v, base, k);
        reg_stage<2>(v, base, k); reg_stage<1>(v, base, k);
        #pragma unroll
        for (int l = 0; l < 16; l++) sk[physi(base + l)] = v[l];
        __syncthreads();
    }

    const float4* anc4 = (const float4*)anc + gb;
    const float4* reg4 = (const float4*)reg + gb;
    for (int j = tid; j < N_BOX; j += TSORT) {
        int i = (int)(unsigned)(sk[physi(j)] & 0xFFFFFFFFull);
        float4 A = anc4[i];
        float4 R = reg4[i];
        float cx = A.z * R.x + A.x;
        float cy = A.w * R.y + A.y;
        float w  = A.z * expf(R.z);
        float h  = A.w * expf(R.w);
        float x1 = fminf(fmaxf(cx - w * 0.5f, 0.f), maxx);
        float x2 = fminf(fmaxf(cx + w * 0.5f, 0.f), maxx);
        float y1 = fminf(fmaxf(cy - h * 0.5f, 0.f), maxy);
        float y2 = fminf(fmaxf(cy + h * 0.5f, 0.f), maxy);
        g_box [gb + j] = make_float4(x1, y1, x2, y2);
        g_area[gb + j] = (x2 - x1) * (y2 - y1);
    }
}

// ------------------------------------------------------------------
// Kernel 2: sparse suppression-bitmask generation — BRANCH-FREE inner loop
// block = 256 rows x 256 cols; per-lane row, broadcast columns
// ------------------------------------------------------------------
__global__ __launch_bounds__(256)
void maskgen_kernel()
{
    const int rt = blockIdx.x;
    const int cg = blockIdx.y;
    const int b  = blockIdx.z;
    if (cg < rt) return;

    const int rowbase = rt << 8;
    const int colbase = cg << 8;

    __shared__ float4 s_cb[256];
    __shared__ float  s_ca[256];
    const int tid = threadIdx.x;
    const size_t gb = (size_t)b * N_BOX;

    s_cb[tid] = g_box [gb + colbase + tid];
    s_ca[tid] = g_area[gb + colbase + tid];
    __syncthreads();

    const int    i   = rowbase + tid;
    const float4 rb  = g_box [gb + i];
    const float  ra  = g_area[gb + i];
    const int    myw = i >> 6;

    #pragma unroll
    for (int w = 0; w < 4; w++) {
        const int ct = (cg << 2) + w;
        if (ct < myw) continue;          // strictly below diagonal (diag tiles only)

        unsigned half_acc[2];
        #pragma unroll
        for (int h = 0; h < 2; h++) {
            const int cb0 = (w << 6) + (h << 5);
            unsigned acc = 0, unc = 0;
            #pragma unroll 8
            for (int cc = 0; cc < 32; cc++) {
                float4 cb = s_cb[cb0 + cc];
                float  ca = s_ca[cb0 + cc];
                float iw = fminf(rb.z, cb.z) - fmaxf(rb.x, cb.x);
                float ih = fminf(rb.w, cb.w) - fmaxf(rb.y, cb.y);
                float inter = fmaxf(iw, 0.f) * fmaxf(ih, 0.f);
                float denom = ra + ca - inter + 1e-9f;
                bool hib = inter > 0.714f * denom;                      // certainly suppressed
                bool unb = (!hib) && (inter >= 0.686f * denom);         // needs exact check
                acc |= hib ? (1u << cc) : 0u;
                unc |= unb ? (1u << cc) : 0u;
            }
            // rare exact fixup (probability ~1e-4 per pair)
            if (unc) {
                unsigned u = unc;
                while (u) {
                    int cc = __ffs(u) - 1; u &= u - 1;
                    float4 cb = s_cb[cb0 + cc];
                    float  ca = s_ca[cb0 + cc];
                    float iw = fminf(rb.z, cb.z) - fmaxf(rb.x, cb.x);
                    float ih = fminf(rb.w, cb.w) - fmaxf(rb.y, cb.y);
                    float inter = fmaxf(iw, 0.f) * fmaxf(ih, 0.f);
                    float denom = ra + ca - inter + 1e-9f;
                    float iou = inter / denom;
                    if (iou > NMS_TH) acc |= 1u << cc;
                }
            }
            half_acc[h] = acc;
        }

        u64 bits = ((u64)half_acc[1] << 32) | half_acc[0];

        if (ct == myw) {
            // keep only columns strictly right of the diagonal
            int s = (i & 63) + 1;
            u64 m = (s >= 64) ? 0ull : (~0ull << s);
            g_diag[gb + i] = bits & m;
        } else if (bits) {
            g_mask[(gb + i) * NW + ct] = bits;
            atomicOr(&g_sum[((gb + i) << 2) + (ct >> 6)], 1ull << (ct & 63));
        }
    }
}

// ------------------------------------------------------------------
// Kernel 3: sparse sequential greedy resolution + emit
// ------------------------------------------------------------------
__global__ __launch_bounds__(NW, 1)
void resolve_kernel(float* __restrict__ out, int B)
{
    __shared__ u64 remv [NW];
    __shared__ u64 keepw[NW];
    __shared__ u64 sdiag[2][64];
    __shared__ u64 ssum [2][256];
    __shared__ u64 s_kept;
    __shared__ int s_scan[NW];

    const int b   = blockIdx.x;
    const int tid = threadIdx.x;
    const size_t gb = (size_t)b * N_BOX;

    float* obox = out;
    float* oidx = out + (size_t)B * POST * 4;
    float* oval = oidx + (size_t)B * POST;

    for (int r = tid; r < POST; r += NW) {
        size_t o = ((size_t)b * POST + r) * 4;
        obox[o + 0] = 0.f; obox[o + 1] = 0.f; obox[o + 2] = 0.f; obox[o + 3] = 0.f;
        oidx[(size_t)b * POST + r] = -1.0f;
        oval[(size_t)b * POST + r] = 0.0f;
    }
    remv[tid] = 0ull;

    if (tid < 64) sdiag[0][tid] = g_diag[gb + tid];
    ssum[0][tid] = g_sum[(gb << 2) + tid];
    __syncthreads();

    for (int c = 0; c < NW; c++) {
        const int buf = c & 1, nb = buf ^ 1;

        if (c + 1 < NW) {
            const int nbase = (c + 1) << 6;
            if (tid < 64) sdiag[nb][tid] = g_diag[gb + nbase + tid];
            ssum[nb][tid] = g_sum[((gb + nbase) << 2) + tid];
        }

        if (tid == 0) {
            u64 kept = 0;
            u64 und  = ~remv[c];
            while (und) {
                int r = __ffsll((long long)und) - 1;
                kept |= 1ull << r;
                u64 d = sdiag[buf][r];
                und &= ~(d | (1ull << r));
            }
            keepw[c] = kept;
            s_kept   = kept;
        }
        __syncthreads();

        const u64 kb = s_kept;
        if (tid < 64 && ((kb >> tid) & 1ull)) {
            const int row = (c << 6) + tid;
            const u64* sp = &ssum[buf][tid << 2];
            #pragma unroll
            for (int j = 0; j < 4; j++) {
                u64 s = sp[j];
                while (s) {
                    int k = (j << 6) + __ffsll((long long)s) - 1;
                    s &= s - 1;
                    atomicOr(&remv[k], g_mask[(gb + row) * NW + k]);
                }
            }
        }
        __syncthreads();
    }

    s_scan[tid] = __popcll(keepw[tid]);
    __syncthreads();
    for (int off = 1; off < NW; off <<= 1) {
        int vv = s_scan[tid];
        if (tid >= off) vv += s_scan[tid - off];
        __syncthreads();
        s_scan[tid] = vv;
        __syncthreads();
    }
    {
        u64 kw = keepw[tid];
        int r = s_scan[tid] - __popcll(kw);
        const int base = tid << 6;
        while (kw && r < POST) {
            int rr = __ffsll((long long)kw) - 1;
            kw &= kw - 1;
            int j = base + rr;
            float4 bx = g_box[gb + j];
            size_t o = ((size_t)b * POST + r) * 4;
            obox[o + 0] = bx.x; obox[o + 1] = bx.y;
            obox[o + 2] = bx.z; obox[o + 3] = bx.w;
            oidx[(size_t)b * POST + r] = (float)j;
            oval[(size_t)b * POST + r] = 1.0f;
            r++;
        }
    }
}

// ------------------------------------------------------------------
extern "C" void kernel_launch(void* const* d_in, const int* in_sizes, int n_in,
                              void* d_out, int out_size)
{
    const float* fg  = (const float*)d_in[0];
    const float* reg = (const float*)d_in[1];
    const float* anc = (const float*)d_in[2];
    const int*   ph  = (const int*)d_in[3];
    const int*   pw  = (const int*)d_in[4];

    int B = in_sizes[0] / N_BOX;
    if (B < 1) B = 1;
    if (B > MAX_B) B = MAX_B;

    const int SORT_SMEM = (N_BOX + N_BOX / 16) * (int)sizeof(u64);
    cudaFuncSetAttribute(sort_decode_kernel,
                         cudaFuncAttributeMaxDynamicSharedMemorySize, SORT_SMEM);

    zero_sum_kernel<<<512, 256>>>();
    sort_decode_kernel<<<B, TSORT, SORT_SMEM>>>(fg, reg, anc, ph, pw);
    maskgen_kernel<<<dim3(N_BOX / 256, N_BOX / 256, B), 256>>>();
    resolve_kernel<<<B, NW>>>((float*)d_out, B);
}

// round 5
// speedup vs baseline: 81.1562x; 7.9393x over previous
#include <cuda_runtime.h>
#include <cstdint>

typedef unsigned long long u64;

#define N_BOX   16384
#define TSORT   1024
#define POST    1000
#define NMS_TH  0.7f
#define MAX_B   8
#define NW      256            // 64-bit words per full mask row
#define PRE     2048           // prefix length (must be mult of 256)
#define PNW     (PRE / 64)     // 32 prefix words

#define CBASE 0.4117647058823529f     // 0.7/1.7
#define CHI   (CBASE * 1.02f)
#define CLO   (CBASE * 0.98f)

// Global scratch (allocation-free rule -> __device__ globals)
__device__ float4 g_box [MAX_B * N_BOX];
__device__ float  g_area[MAX_B * N_BOX];
__device__ u64    g_mask[(size_t)MAX_B * N_BOX * NW];   // sparse: nonzero words only (gated by g_sum)
__device__ u64    g_diag[MAX_B * N_BOX];                // diagonal word per row
__device__ u64    g_sum [MAX_B * N_BOX * 4];            // per-row summary of nonzero tail words
__device__ int    g_done[MAX_B];                        // prefix path succeeded

__device__ __forceinline__ int physi(int i) { return i + (i >> 4); }

// ------------------------------------------------------------------
// Kernel 1: per-batch stable sort (score desc, idx asc) + decode/clip
// ------------------------------------------------------------------
template<int JJ>
__device__ __forceinline__ void reg_stage(u64 v[16], int base, int k)
{
    #pragma unroll
    for (int l = 0; l < 16; l++) if ((l & JJ) == 0) {
        const int p = l | JJ;
        bool up = (((base + l) & k) == 0);
        u64 a = v[l], c = v[p];
        if ((a > c) == up) { v[l] = c; v[p] = a; }
    }
}

__global__ __launch_bounds__(TSORT, 1)
void sort_decode_kernel(const float* __restrict__ fg,
                        const float* __restrict__ reg,
                        const float* __restrict__ anc,
                        const int*   __restrict__ p_h,
                        const int*   __restrict__ p_w)
{
    extern __shared__ u64 sk[];
    const int b   = blockIdx.x;
    const int tid = threadIdx.x;
    const size_t gb = (size_t)b * N_BOX;

    int hv = *p_h, wv = *p_w;
    int H = (hv > 0 && hv < 1000000) ? hv : (int)__int_as_float(hv);
    int W = (wv > 0 && wv < 1000000) ? wv : (int)__int_as_float(wv);
    const float maxy = (float)H - 1.0f;
    const float maxx = (float)W - 1.0f;

    const float* fgb = fg + gb;
    for (int j = tid; j < N_BOX; j += TSORT) {
        unsigned u   = __float_as_uint(fgb[j]);
        unsigned asc = u ^ ((u >> 31) ? 0xFFFFFFFFu : 0x80000000u);
        sk[physi(j)] = ((u64)(~asc) << 32) | (unsigned)j;
    }
    __syncthreads();

    const int base = tid * 16;
    u64 v[16];
    #pragma unroll
    for (int l = 0; l < 16; l++) v[l] = sk[physi(base + l)];
    reg_stage<1>(v, base, 2);
    reg_stage<2>(v, base, 4);  reg_stage<1>(v, base, 4);
    reg_stage<4>(v, base, 8);  reg_stage<2>(v, base, 8);  reg_stage<1>(v, base, 8);
    reg_stage<8>(v, base, 16); reg_stage<4>(v, base, 16); reg_stage<2>(v, base, 16); reg_stage<1>(v, base, 16);
    #pragma unroll
    for (int l = 0; l < 16; l++) sk[physi(base + l)] = v[l];
    __syncthreads();

    for (int k = 32; k <= N_BOX; k <<= 1) {
        for (int jj = k >> 1; jj >= 16; jj >>= 1) {
            for (int s = tid; s < N_BOX / 2; s += TSORT) {
                int i  = ((s & ~(jj - 1)) << 1) | (s & (jj - 1));
                int j2 = i | jj;
                bool up = ((i & k) == 0);
                int pi = physi(i), pj = physi(j2);
                u64 a = sk[pi], c = sk[pj];
                if ((a > c) == up) { sk[pi] = c; sk[pj] = a; }
            }
            __syncthreads();
        }
        #pragma unroll
        for (int l = 0; l < 16; l++) v[l] = sk[physi(base + l)];
        reg_stage<8>(v, base, k); reg_stage<4>(v, base, k);
        reg_stage<2>(v, base, k); reg_stage<1>(v, base, k);
        #pragma unroll
        for (int l = 0; l < 16; l++) sk[physi(base + l)] = v[l];
        __syncthreads();
    }

    const float4* anc4 = (const float4*)anc + gb;
    const float4* reg4 = (const float4*)reg + gb;
    for (int j = tid; j < N_BOX; j += TSORT) {
        int i = (int)(unsigned)(sk[physi(j)] & 0xFFFFFFFFull);
        float4 A = anc4[i];
        float4 R = reg4[i];
        float cx = A.z * R.x + A.x;
        float cy = A.w * R.y + A.y;
        float w  = A.z * expf(R.z);
        float h  = A.w * expf(R.w);
        float x1 = fminf(fmaxf(cx - w * 0.5f, 0.f), maxx);
        float x2 = fminf(fmaxf(cx + w * 0.5f, 0.f), maxx);
        float y1 = fminf(fmaxf(cy - h * 0.5f, 0.f), maxy);
        float y2 = fminf(fmaxf(cy + h * 0.5f, 0.f), maxy);
        g_box [gb + j] = make_float4(x1, y1, x2, y2);
        g_area[gb + j] = (x2 - x1) * (y2 - y1);
    }
}

// ------------------------------------------------------------------
// Kernel 2: suppression bitmask generation (prefix grid or gated full grid)
// 256 rows x 256 cols per block; transformed-threshold branch-free loop
// ------------------------------------------------------------------
__global__ __launch_bounds__(256)
void maskgen_kernel(int gated)
{
    const int b = blockIdx.z;
    if (gated && g_done[b]) return;
    const int rt = blockIdx.x;
    const int cg = blockIdx.y;
    if (cg < rt) return;

    const int rowbase = rt << 8;
    const int colbase = cg << 8;

    __shared__ float4 s_cb[256];
    __shared__ float2 s_kc[256];   // (CHI*ca, CLO*ca)
    __shared__ float  s_ca[256];
    const int tid = threadIdx.x;
    const size_t gb = (size_t)b * N_BOX;

    {
        float4 cb = g_box [gb + colbase + tid];
        float  ca = g_area[gb + colbase + tid];
        s_cb[tid] = cb;
        s_ca[tid] = ca;
        s_kc[tid] = make_float2(CHI * ca, CLO * ca);
    }
    __syncthreads();

    const int    i   = rowbase + tid;
    const float4 rb  = g_box [gb + i];
    const float  ra  = g_area[gb + i];
    const float  uhi = CHI * (ra + 1e-9f);
    const float  ulo = CLO * (ra + 1e-9f);
    const int    myw = i >> 6;

    #pragma unroll
    for (int w = 0; w < 4; w++) {
        const int ct = (cg << 2) + w;
        if (ct < myw) continue;

        unsigned acc_h[2], unc_h[2];
        #pragma unroll
        for (int h = 0; h < 2; h++) {
            const int cb0 = (w << 6) + (h << 5);
            unsigned acc = 0, unc = 0;
            #pragma unroll 16
            for (int cc = 31; cc >= 0; cc--) {
                float4 cb = s_cb[cb0 + cc];
                float2 kc = s_kc[cb0 + cc];
                float iw = fminf(rb.z, cb.z) - fmaxf(rb.x, cb.x);
                float ih = fminf(rb.w, cb.w) - fmaxf(rb.y, cb.y);
                float inter = fmaxf(iw, 0.f) * fmaxf(ih, 0.f);
                bool hib = inter > (uhi + kc.x);
                bool unb = (!hib) && (inter >= (ulo + kc.y));
                acc = acc * 2u + (hib ? 1u : 0u);
                unc = unc * 2u + (unb ? 1u : 0u);
            }
            acc_h[h] = acc; unc_h[h] = unc;
        }

        u64 bits = ((u64)acc_h[1] << 32) | acc_h[0];
        u64 unc64 = ((u64)unc_h[1] << 32) | unc_h[0];

        // rare exact fixup band: evaluate reference expression verbatim
        while (unc64) {
            int cc = __ffsll((long long)unc64) - 1; unc64 &= unc64 - 1;
            float4 cb = s_cb[(w << 6) + cc];
            float  ca = s_ca[(w << 6) + cc];
            float iw = fminf(rb.z, cb.z) - fmaxf(rb.x, cb.x);
            float ih = fminf(rb.w, cb.w) - fmaxf(rb.y, cb.y);
            float inter = fmaxf(iw, 0.f) * fmaxf(ih, 0.f);
            float iou = inter / (ra + ca - inter + 1e-9f);
            if (iou > NMS_TH) bits |= 1ull << cc;
        }

        if (ct == myw) {
            int s = (i & 63) + 1;
            u64 m = (s >= 64) ? 0ull : (~0ull << s);
            g_diag[gb + i] = bits & m;
        } else if (bits) {
            g_mask[(gb + i) * NW + ct] = bits;
            atomicOr(&g_sum[((gb + i) << 2) + (ct >> 6)], 1ull << (ct & 63));
        }
    }
}

// ------------------------------------------------------------------
// Kernel 3a: prefix resolve — if >=1000 kept in first PRE boxes, emit & done
// ------------------------------------------------------------------
__global__ __launch_bounds__(256, 1)
void resolve_prefix_kernel(float* __restrict__ out, int B)
{
    __shared__ u64      sdiag[PRE];          // 16 KB
    __shared__ unsigned ss0  [PRE];          // 8 KB: low 32 bits of g_sum word0
    __shared__ u64      remv [PNW];
    __shared__ u64      keepw[PNW];
    __shared__ u64      s_kept;
    __shared__ int      s_scan[PNW];
    __shared__ int      s_total;

    const int b   = blockIdx.x;
    const int tid = threadIdx.x;
    const size_t gb = (size_t)b * N_BOX;

    for (int j = tid; j < PRE; j += 256) {
        sdiag[j] = g_diag[gb + j];
        ss0[j]   = (unsigned)g_sum[(gb + j) << 2];
    }
    if (tid < PNW) remv[tid] = 0ull;
    __syncthreads();

    for (int c = 0; c < PNW; c++) {
        if (tid == 0) {
            u64 kept = 0;
            u64 und  = ~remv[c];
            const u64* d = &sdiag[c << 6];
            while (und) {
                int r = __ffsll((long long)und) - 1;
                kept |= 1ull << r;
                und &= ~(d[r] | (1ull << r));
            }
            keepw[c] = kept;
            s_kept   = kept;
        }
        __syncthreads();
        const u64 kb = s_kept;
        if (tid < 64 && ((kb >> tid) & 1ull)) {
            const int row = (c << 6) + tid;
            unsigned s = ss0[row] & ~((c + 1 < 32) ? ((1u << (c + 1)) - 1u) : 0xFFFFFFFFu);
            // only tail words k in (c, PNW)
            s &= (PNW < 32) ? ((1u << PNW) - 1u) : 0xFFFFFFFFu;
            while (s) {
                int k = __ffs(s) - 1; s &= s - 1;
                atomicOr(&remv[k], g_mask[(gb + row) * NW + k]);
            }
        }
        __syncthreads();
    }

    // count kept
    if (tid < 32) {
        int cnt = __popcll(keepw[tid]);
        int sc = cnt;
        #pragma unroll
        for (int off = 1; off < 32; off <<= 1) {
            int t = __shfl_up_sync(0xffffffffu, sc, off);
            if (tid >= off) sc += t;
        }
        s_scan[tid] = sc;                    // inclusive scan
        if (tid == 31) s_total = sc;
    }
    __syncthreads();

    const int total = s_total;
    if (tid == 0) g_done[b] = (total >= POST) ? 1 : 0;
    if (total < POST) return;                // fall back to full path

    float* obox = out;
    float* oidx = out + (size_t)B * POST * 4;
    float* oval = oidx + (size_t)B * POST;

    if (tid < 32) {
        u64 kw = keepw[tid];
        int r = s_scan[tid] - __popcll(kw);  // exclusive prefix
        const int base = tid << 6;
        while (kw && r < POST) {
            int rr = __ffsll((long long)kw) - 1;
            kw &= kw - 1;
            int j = base + rr;
            float4 bx = g_box[gb + j];
            size_t o = ((size_t)b * POST + r) * 4;
            obox[o + 0] = bx.x; obox[o + 1] = bx.y;
            obox[o + 2] = bx.z; obox[o + 3] = bx.w;
            oidx[(size_t)b * POST + r] = (float)j;
            oval[(size_t)b * POST + r] = 1.0f;
            r++;
        }
    }
}

// ------------------------------------------------------------------
// Kernel 3b: full resolve (fallback only)
// ------------------------------------------------------------------
__global__ __launch_bounds__(NW, 1)
void resolve_full_kernel(float* __restrict__ out, int B)
{
    const int b = blockIdx.x;
    if (g_done[b]) return;

    __shared__ u64 remv [NW];
    __shared__ u64 keepw[NW];
    __shared__ u64 sdiag[2][64];
    __shared__ u64 ssum [2][256];
    __shared__ u64 s_kept;
    __shared__ int s_scan[NW];

    const int tid = threadIdx.x;
    const size_t gb = (size_t)b * N_BOX;

    float* obox = out;
    float* oidx = out + (size_t)B * POST * 4;
    float* oval = oidx + (size_t)B * POST;

    for (int r = tid; r < POST; r += NW) {
        size_t o = ((size_t)b * POST + r) * 4;
        obox[o + 0] = 0.f; obox[o + 1] = 0.f; obox[o + 2] = 0.f; obox[o + 3] = 0.f;
        oidx[(size_t)b * POST + r] = -1.0f;
        oval[(size_t)b * POST + r] = 0.0f;
    }
    remv[tid] = 0ull;

    if (tid < 64) sdiag[0][tid] = g_diag[gb + tid];
    ssum[0][tid] = g_sum[(gb << 2) + tid];
    __syncthreads();

    for (int c = 0; c < NW; c++) {
        const int buf = c & 1, nb = buf ^ 1;
        if (c + 1 < NW) {
            const int nbase = (c + 1) << 6;
            if (tid < 64) sdiag[nb][tid] = g_diag[gb + nbase + tid];
            ssum[nb][tid] = g_sum[((gb + nbase) << 2) + tid];
        }
        if (tid == 0) {
            u64 kept = 0;
            u64 und  = ~remv[c];
            while (und) {
                int r = __ffsll((long long)und) - 1;
                kept |= 1ull << r;
                und &= ~(sdiag[buf][r] | (1ull << r));
            }
            keepw[c] = kept;
            s_kept   = kept;
        }
        __syncthreads();
        const u64 kb = s_kept;
        if (tid < 64 && ((kb >> tid) & 1ull)) {
            const int row = (c << 6) + tid;
            const u64* sp = &ssum[buf][tid << 2];
            #pragma unroll
            for (int j = 0; j < 4; j++) {
                u64 s = sp[j];
                while (s) {
                    int k = (j << 6) + __ffsll((long long)s) - 1;
                    s &= s - 1;
                    atomicOr(&remv[k], g_mask[(gb + row) * NW + k]);
                }
            }
        }
        __syncthreads();
    }

    s_scan[tid] = __popcll(keepw[tid]);
    __syncthreads();
    for (int off = 1; off < NW; off <<= 1) {
        int vv = s_scan[tid];
        if (tid >= off) vv += s_scan[tid - off];
        __syncthreads();
        s_scan[tid] = vv;
        __syncthreads();
    }
    {
        u64 kw = keepw[tid];
        int r = s_scan[tid] - __popcll(kw);
        const int base = tid << 6;
        while (kw && r < POST) {
            int rr = __ffsll((long long)kw) - 1;
            kw &= kw - 1;
            int j = base + rr;
            float4 bx = g_box[gb + j];
            size_t o = ((size_t)b * POST + r) * 4;
            obox[o + 0] = bx.x; obox[o + 1] = bx.y;
            obox[o + 2] = bx.z; obox[o + 3] = bx.w;
            oidx[(size_t)b * POST + r] = (float)j;
            oval[(size_t)b * POST + r] = 1.0f;
            r++;
        }
    }
}

// ------------------------------------------------------------------
extern "C" void kernel_launch(void* const* d_in, const int* in_sizes, int n_in,
                              void* d_out, int out_size)
{
    const float* fg  = (const float*)d_in[0];
    const float* reg = (const float*)d_in[1];
    const float* anc = (const float*)d_in[2];
    const int*   ph  = (const int*)d_in[3];
    const int*   pw  = (const int*)d_in[4];

    int B = in_sizes[0] / N_BOX;
    if (B < 1) B = 1;
    if (B > MAX_B) B = MAX_B;

    const int SORT_SMEM = (N_BOX + N_BOX / 16) * (int)sizeof(u64);
    cudaFuncSetAttribute(sort_decode_kernel,
                         cudaFuncAttributeMaxDynamicSharedMemorySize, SORT_SMEM);

    sort_decode_kernel<<<B, TSORT, SORT_SMEM>>>(fg, reg, anc, ph, pw);
    // prefix mask (always)
    maskgen_kernel<<<dim3(PRE / 256, PRE / 256, B), 256>>>(0);
    // prefix resolve: emits + sets g_done if >=1000 kept within prefix
    resolve_prefix_kernel<<<B, 256>>>((float*)d_out, B);
    // full fallback (gated; early-returns when prefix succeeded)
    maskgen_kernel<<<dim3(N_BOX / 256, N_BOX / 256, B), 256>>>(1);
    resolve_full_kernel<<<B, NW>>>((float*)d_out, B);
}

// round 6
// speedup vs baseline: 106.7244x; 1.3150x over previous
#include <cuda_runtime.h>
#include <cstdint>

typedef unsigned long long u64;

#define N_BOX   16384
#define TSORT   1024
#define POST    1000
#define NMS_TH  0.7f
#define MAX_B   8
#define NW      256            // 64-bit words per full mask row
#define PRE     2048           // prefix length
#define PNW     (PRE / 64)     // 32 prefix words
#define NSEL    4096           // candidate sort size

#define CBASE 0.4117647058823529f     // 0.7/1.7
#define CHI   (CBASE * 1.02f)
#define CLO   (CBASE * 0.98f)

// Global scratch (allocation-free rule -> __device__ globals)
__device__ float4 g_box [MAX_B * N_BOX];
__device__ float  g_area[MAX_B * N_BOX];
__device__ u64    g_mask[(size_t)MAX_B * N_BOX * NW];
__device__ u64    g_diag[MAX_B * N_BOX];
__device__ u64    g_sum [MAX_B * N_BOX * 4];
__device__ int    g_done  [MAX_B];     // prefix path produced final output
__device__ int    g_sel_ok[MAX_B];     // top-2048 selection succeeded

__device__ __forceinline__ int physi(int i) { return i + (i >> 4); }

__device__ __forceinline__ unsigned score_key(float f)
{
    unsigned u   = __float_as_uint(f);
    unsigned asc = u ^ ((u >> 31) ? 0xFFFFFFFFu : 0x80000000u);
    return ~asc;                       // ascending dsc == descending score
}

__device__ __forceinline__ void decode_store(size_t gb, int j, int i,
                                             const float4* anc4, const float4* reg4,
                                             float maxx, float maxy)
{
    float4 A = anc4[i];
    float4 R = reg4[i];
    float cx = A.z * R.x + A.x;
    float cy = A.w * R.y + A.y;
    float w  = A.z * expf(R.z);
    float h  = A.w * expf(R.w);
    float x1 = fminf(fmaxf(cx - w * 0.5f, 0.f), maxx);
    float x2 = fminf(fmaxf(cx + w * 0.5f, 0.f), maxx);
    float y1 = fminf(fmaxf(cy - h * 0.5f, 0.f), maxy);
    float y2 = fminf(fmaxf(cy + h * 0.5f, 0.f), maxy);
    g_box [gb + j] = make_float4(x1, y1, x2, y2);
    g_area[gb + j] = (x2 - x1) * (y2 - y1);
}

// ------------------------------------------------------------------
// Kernel A: top-2048 selection + sort-4096 + decode (per batch block)
// ------------------------------------------------------------------
__global__ __launch_bounds__(1024, 1)
void select_kernel(const float* __restrict__ fg,
                   const float* __restrict__ reg,
                   const float* __restrict__ anc,
                   const int*   __restrict__ p_h,
                   const int*   __restrict__ p_w)
{
    __shared__ u64      keys[NSEL + NSEL / 16];   // skewed, 34.8 KB
    __shared__ unsigned hist[2048];               // 8 KB
    __shared__ int      sc  [1024];               // 4 KB
    __shared__ int      s_T, s_Clt, s_cnt_lt, s_cnt_eq, s_fail;

    const int b   = blockIdx.x;
    const int tid = threadIdx.x;
    const size_t gb = (size_t)b * N_BOX;
    const float* fgb = fg + gb;

    hist[tid] = 0u; hist[tid + 1024] = 0u;
    if (tid == 0) { s_cnt_lt = 0; s_cnt_eq = 0; s_fail = 0; }
    __syncthreads();

    // histogram of top-11 key bits
    for (int j = tid; j < N_BOX; j += 1024)
        atomicAdd(&hist[score_key(fgb[j]) >> 21], 1u);
    __syncthreads();

    // block scan over 1024 bin-pairs -> find cutoff bin T and count below
    const unsigned h0 = hist[2 * tid], h1 = hist[2 * tid + 1];
    int v = (int)(h0 + h1);
    sc[tid] = v;
    __syncthreads();
    for (int off = 1; off < 1024; off <<= 1) {
        int vv = sc[tid];
        if (tid >= off) vv += sc[tid - off];
        __syncthreads();
        sc[tid] = vv;
        __syncthreads();
    }
    {
        int inc = sc[tid];
        int cb  = inc - v;                         // exclusive prefix
        if (cb < PRE && inc >= PRE) {
            if (cb + (int)h0 >= PRE) { s_T = 2 * tid;     s_Clt = cb; }
            else                     { s_T = 2 * tid + 1; s_Clt = cb + (int)h0; }
        }
    }
    __syncthreads();
    const int T = s_T, Clt = s_Clt;
    const int M = Clt + (int)hist[T];
    if (M > NSEL) {                               // adversarial ties -> full path
        if (tid == 0) { g_sel_ok[b] = 0; }
        return;
    }

    // compact candidates (warp-aggregated)
    const int lane = tid & 31;
    for (int j = tid; j < N_BOX; j += 1024) {
        unsigned dsc = score_key(fgb[j]);
        int bin = (int)(dsc >> 21);
        bool plt = bin < T, peq = bin == T;
        unsigned mlt = __ballot_sync(0xffffffffu, plt);
        unsigned meq = __ballot_sync(0xffffffffu, peq);
        int blt = 0, beq = 0;
        if (lane == 0) {
            if (mlt) blt = atomicAdd(&s_cnt_lt, __popc(mlt));
            if (meq) beq = atomicAdd(&s_cnt_eq, __popc(meq));
        }
        blt = __shfl_sync(0xffffffffu, blt, 0);
        beq = __shfl_sync(0xffffffffu, beq, 0);
        unsigned below = (1u << lane) - 1u;
        u64 key = ((u64)dsc << 32) | (unsigned)j;
        if (plt) keys[physi(blt + __popc(mlt & below))]       = key;
        if (peq) keys[physi(Clt + beq + __popc(meq & below))] = key;
    }
    __syncthreads();
    for (int p = M + tid; p < NSEL; p += 1024) keys[physi(p)] = ~0ull;
    __syncthreads();

    // bitonic sort 4096 (ascending)
    for (int k = 2; k <= NSEL; k <<= 1) {
        for (int jj = k >> 1; jj > 0; jj >>= 1) {
            #pragma unroll
            for (int t = 0; t < 2; t++) {
                int s  = tid + t * 1024;
                int i  = ((s & ~(jj - 1)) << 1) | (s & (jj - 1));
                int j2 = i | jj;
                bool up = ((i & k) == 0);
                int pi = physi(i), pj = physi(j2);
                u64 a = keys[pi], c = keys[pj];
                if ((a > c) == up) { keys[pi] = c; keys[pj] = a; }
            }
            __syncthreads();
        }
    }

    // decode top-2048 in sorted order
    int hv = *p_h, wv = *p_w;
    int H = (hv > 0 && hv < 1000000) ? hv : (int)__int_as_float(hv);
    int W = (wv > 0 && wv < 1000000) ? wv : (int)__int_as_float(wv);
    const float maxy = (float)H - 1.0f;
    const float maxx = (float)W - 1.0f;
    const float4* anc4 = (const float4*)anc + gb;
    const float4* reg4 = (const float4*)reg + gb;
    #pragma unroll
    for (int t = 0; t < 2; t++) {
        int j = tid + t * 1024;
        int i = (int)(unsigned)(keys[physi(j)] & 0xFFFFFFFFull);
        decode_store(gb, j, i, anc4, reg4, maxx, maxy);
    }
    if (tid == 0) g_sel_ok[b] = 1;
}

// ------------------------------------------------------------------
// Kernel B (fallback): full per-batch stable sort + decode (gated)
// ------------------------------------------------------------------
template<int JJ>
__device__ __forceinline__ void reg_stage(u64 v[16], int base, int k)
{
    #pragma unroll
    for (int l = 0; l < 16; l++) if ((l & JJ) == 0) {
        const int p = l | JJ;
        bool up = (((base + l) & k) == 0);
        u64 a = v[l], c = v[p];
        if ((a > c) == up) { v[l] = c; v[p] = a; }
    }
}

__global__ __launch_bounds__(TSORT, 1)
void sort_decode_full_kernel(const float* __restrict__ fg,
                             const float* __restrict__ reg,
                             const float* __restrict__ anc,
                             const int*   __restrict__ p_h,
                             const int*   __restrict__ p_w)
{
    const int b = blockIdx.x;
    if (g_done[b]) return;

    extern __shared__ u64 sk[];
    const int tid = threadIdx.x;
    const size_t gb = (size_t)b * N_BOX;

    int hv = *p_h, wv = *p_w;
    int H = (hv > 0 && hv < 1000000) ? hv : (int)__int_as_float(hv);
    int W = (wv > 0 && wv < 1000000) ? wv : (int)__int_as_float(wv);
    const float maxy = (float)H - 1.0f;
    const float maxx = (float)W - 1.0f;

    const float* fgb = fg + gb;
    for (int j = tid; j < N_BOX; j += TSORT)
        sk[physi(j)] = ((u64)score_key(fgb[j]) << 32) | (unsigned)j;
    __syncthreads();

    const int base = tid * 16;
    u64 v[16];
    #pragma unroll
    for (int l = 0; l < 16; l++) v[l] = sk[physi(base + l)];
    reg_stage<1>(v, base, 2);
    reg_stage<2>(v, base, 4);  reg_stage<1>(v, base, 4);
    reg_stage<4>(v, base, 8);  reg_stage<2>(v, base, 8);  reg_stage<1>(v, base, 8);
    reg_stage<8>(v, base, 16); reg_stage<4>(v, base, 16); reg_stage<2>(v, base, 16); reg_stage<1>(v, base, 16);
    #pragma unroll
    for (int l = 0; l < 16; l++) sk[physi(base + l)] = v[l];
    __syncthreads();

    for (int k = 32; k <= N_BOX; k <<= 1) {
        for (int jj = k >> 1; jj >= 16; jj >>= 1) {
            for (int s = tid; s < N_BOX / 2; s += TSORT) {
                int i  = ((s & ~(jj - 1)) << 1) | (s & (jj - 1));
                int j2 = i | jj;
                bool up = ((i & k) == 0);
                int pi = physi(i), pj = physi(j2);
                u64 a = sk[pi], c = sk[pj];
                if ((a > c) == up) { sk[pi] = c; sk[pj] = a; }
            }
            __syncthreads();
        }
        #pragma unroll
        for (int l = 0; l < 16; l++) v[l] = sk[physi(base + l)];
        reg_stage<8>(v, base, k); reg_stage<4>(v, base, k);
        reg_stage<2>(v, base, k); reg_stage<1>(v, base, k);
        #pragma unroll
        for (int l = 0; l < 16; l++) sk[physi(base + l)] = v[l];
        __syncthreads();
    }

    const float4* anc4 = (const float4*)anc + gb;
    const float4* reg4 = (const float4*)reg + gb;
    for (int j = tid; j < N_BOX; j += TSORT) {
        int i = (int)(unsigned)(sk[physi(j)] & 0xFFFFFFFFull);
        decode_store(gb, j, i, anc4, reg4, maxx, maxy);
    }
}

// ------------------------------------------------------------------
// Kernel C: suppression bitmask generation (templated tile / gate)
// ------------------------------------------------------------------
template<int COLTILE, bool PREFIX_MODE>
__global__ __launch_bounds__(256)
void maskgen_kernel_t()
{
    const int b = blockIdx.z;
    if (PREFIX_MODE) { if (!g_sel_ok[b]) return; }
    else             { if (g_done[b])   return; }

    const int rowbase = blockIdx.x << 8;
    const int colbase = blockIdx.y * COLTILE;
    if (colbase + COLTILE <= rowbase) return;   // tile strictly below diagonal

    __shared__ float4 s_cb[COLTILE];
    __shared__ float2 s_kc[COLTILE];
    __shared__ float  s_ca[COLTILE];
    const int tid = threadIdx.x;
    const size_t gb = (size_t)b * N_BOX;

    for (int t = tid; t < COLTILE; t += 256) {
        float4 cb = g_box [gb + colbase + t];
        float  ca = g_area[gb + colbase + t];
        s_cb[t] = cb;
        s_ca[t] = ca;
        s_kc[t] = make_float2(CHI * ca, CLO * ca);
    }
    __syncthreads();

    const int    i   = rowbase + tid;
    const float4 rb  = g_box [gb + i];
    const float  ra  = g_area[gb + i];
    const float  uhi = CHI * (ra + 1e-9f);
    const float  ulo = CLO * (ra + 1e-9f);
    const int    myw = i >> 6;

    #pragma unroll
    for (int w = 0; w < COLTILE / 64; w++) {
        const int ct = (colbase >> 6) + w;
        if (ct < myw) continue;

        unsigned acc_h[2], unc_h[2];
        #pragma unroll
        for (int h = 0; h < 2; h++) {
            const int cb0 = (w << 6) + (h << 5);
            unsigned acc = 0, unc = 0;
            #pragma unroll 16
            for (int cc = 31; cc >= 0; cc--) {
                float4 cb = s_cb[cb0 + cc];
                float2 kc = s_kc[cb0 + cc];
                float iw = fminf(rb.z, cb.z) - fmaxf(rb.x, cb.x);
                float ih = fminf(rb.w, cb.w) - fmaxf(rb.y, cb.y);
                float inter = fmaxf(iw, 0.f) * fmaxf(ih, 0.f);
                bool hib = inter > (uhi + kc.x);
                bool unb = (!hib) && (inter >= (ulo + kc.y));
                acc = acc * 2u + (hib ? 1u : 0u);
                unc = unc * 2u + (unb ? 1u : 0u);
            }
            acc_h[h] = acc; unc_h[h] = unc;
        }

        u64 bits  = ((u64)acc_h[1] << 32) | acc_h[0];
        u64 unc64 = ((u64)unc_h[1] << 32) | unc_h[0];

        while (unc64) {                          // rare exact fixup band
            int cc = __ffsll((long long)unc64) - 1; unc64 &= unc64 - 1;
            float4 cb = s_cb[(w << 6) + cc];
            float  ca = s_ca[(w << 6) + cc];
            float iw = fminf(rb.z, cb.z) - fmaxf(rb.x, cb.x);
            float ih = fminf(rb.w, cb.w) - fmaxf(rb.y, cb.y);
            float inter = fmaxf(iw, 0.f) * fmaxf(ih, 0.f);
            float iou = inter / (ra + ca - inter + 1e-9f);
            if (iou > NMS_TH) bits |= 1ull << cc;
        }

        if (ct == myw) {
            int s = (i & 63) + 1;
            u64 m = (s >= 64) ? 0ull : (~0ull << s);
            g_diag[gb + i] = bits & m;
        } else if (bits) {
            g_mask[(gb + i) * NW + ct] = bits;
            atomicOr(&g_sum[((gb + i) << 2) + (ct >> 6)], 1ull << (ct & 63));
        }
    }
}

// ------------------------------------------------------------------
// Kernel D: prefix resolve — if >=1000 kept in first PRE boxes, emit & done
// ------------------------------------------------------------------
__global__ __launch_bounds__(256, 1)
void resolve_prefix_kernel(float* __restrict__ out, int B)
{
    __shared__ u64      sdiag[PRE];
    __shared__ unsigned ss0  [PRE];
    __shared__ u64      remv [PNW];
    __shared__ u64      keepw[PNW];
    __shared__ u64      s_kept;
    __shared__ int      s_scan[PNW];
    __shared__ int      s_total;

    const int b   = blockIdx.x;
    const int tid = threadIdx.x;
    const size_t gb = (size_t)b * N_BOX;

    if (!g_sel_ok[b]) { if (tid == 0) g_done[b] = 0; return; }

    for (int j = tid; j < PRE; j += 256) {
        sdiag[j] = g_diag[gb + j];
        ss0[j]   = (unsigned)g_sum[(gb + j) << 2];
    }
    if (tid < PNW) remv[tid] = 0ull;
    __syncthreads();

    for (int c = 0; c < PNW; c++) {
        if (tid == 0) {
            u64 kept = 0;
            u64 und  = ~remv[c];
            const u64* d = &sdiag[c << 6];
            while (und) {
                int r = __ffsll((long long)und) - 1;
                kept |= 1ull << r;
                und &= ~(d[r] | (1ull << r));
            }
            keepw[c] = kept;
            s_kept   = kept;
        }
        __syncthreads();
        const u64 kb = s_kept;
        if (tid < 64 && ((kb >> tid) & 1ull)) {
            const int row = (c << 6) + tid;
            unsigned s = ss0[row] & ~((c + 1 < 32) ? ((1u << (c + 1)) - 1u) : 0xFFFFFFFFu);
            while (s) {
                int k = __ffs(s) - 1; s &= s - 1;
                atomicOr(&remv[k], g_mask[(gb + row) * NW + k]);
            }
        }
        __syncthreads();
    }

    if (tid < 32) {
        int cnt = __popcll(keepw[tid]);
        int scv = cnt;
        #pragma unroll
        for (int off = 1; off < 32; off <<= 1) {
            int t = __shfl_up_sync(0xffffffffu, scv, off);
            if (tid >= off) scv += t;
        }
        s_scan[tid] = scv;
        if (tid == 31) s_total = scv;
    }
    __syncthreads();

    const int total = s_total;
    if (tid == 0) g_done[b] = (total >= POST) ? 1 : 0;
    if (total < POST) return;

    float* obox = out;
    float* oidx = out + (size_t)B * POST * 4;
    float* oval = oidx + (size_t)B * POST;

    if (tid < 32) {
        u64 kw = keepw[tid];
        int r = s_scan[tid] - __popcll(kw);
        const int base = tid << 6;
        while (kw && r < POST) {
            int rr = __ffsll((long long)kw) - 1;
            kw &= kw - 1;
            int j = base + rr;
            float4 bx = g_box[gb + j];
            size_t o = ((size_t)b * POST + r) * 4;
            obox[o + 0] = bx.x; obox[o + 1] = bx.y;
            obox[o + 2] = bx.z; obox[o + 3] = bx.w;
            oidx[(size_t)b * POST + r] = (float)j;
            oval[(size_t)b * POST + r] = 1.0f;
            r++;
        }
    }
}

// ------------------------------------------------------------------
// Kernel E: full resolve (fallback only)
// ------------------------------------------------------------------
__global__ __launch_bounds__(NW, 1)
void resolve_full_kernel(float* __restrict__ out, int B)
{
    const int b = blockIdx.x;
    if (g_done[b]) return;

    __shared__ u64 remv [NW];
    __shared__ u64 keepw[NW];
    __shared__ u64 sdiag[2][64];
    __shared__ u64 ssum [2][256];
    __shared__ u64 s_kept;
    __shared__ int s_scan[NW];

    const int tid = threadIdx.x;
    const size_t gb = (size_t)b * N_BOX;

    float* obox = out;
    float* oidx = out + (size_t)B * POST * 4;
    float* oval = oidx + (size_t)B * POST;

    for (int r = tid; r < POST; r += NW) {
        size_t o = ((size_t)b * POST + r) * 4;
        obox[o + 0] = 0.f; obox[o + 1] = 0.f; obox[o + 2] = 0.f; obox[o + 3] = 0.f;
        oidx[(size_t)b * POST + r] = -1.0f;
        oval[(size_t)b * POST + r] = 0.0f;
    }
    remv[tid] = 0ull;

    if (tid < 64) sdiag[0][tid] = g_diag[gb + tid];
    ssum[0][tid] = g_sum[(gb << 2) + tid];
    __syncthreads();

    for (int c = 0; c < NW; c++) {
        const int buf = c & 1, nb = buf ^ 1;
        if (c + 1 < NW) {
            const int nbase = (c + 1) << 6;
            if (tid < 64) sdiag[nb][tid] = g_diag[gb + nbase + tid];
            ssum[nb][tid] = g_sum[((gb + nbase) << 2) + tid];
        }
        if (tid == 0) {
            u64 kept = 0;
            u64 und  = ~remv[c];
            while (und) {
                int r = __ffsll((long long)und) - 1;
                kept |= 1ull << r;
                und &= ~(sdiag[buf][r] | (1ull << r));
            }
            keepw[c] = kept;
            s_kept   = kept;
        }
        __syncthreads();
        const u64 kb = s_kept;
        if (tid < 64 && ((kb >> tid) & 1ull)) {
            const int row = (c << 6) + tid;
            const u64* sp = &ssum[buf][tid << 2];
            #pragma unroll
            for (int j = 0; j < 4; j++) {
                u64 s = sp[j];
                while (s) {
                    int k = (j << 6) + __ffsll((long long)s) - 1;
                    s &= s - 1;
                    atomicOr(&remv[k], g_mask[(gb + row) * NW + k]);
                }
            }
        }
        __syncthreads();
    }

    s_scan[tid] = __popcll(keepw[tid]);
    __syncthreads();
    for (int off = 1; off < NW; off <<= 1) {
        int vv = s_scan[tid];
        if (tid >= off) vv += s_scan[tid - off];
        __syncthreads();
        s_scan[tid] = vv;
        __syncthreads();
    }
    {
        u64 kw = keepw[tid];
        int r = s_scan[tid] - __popcll(kw);
        const int base = tid << 6;
        while (kw && r < POST) {
            int rr = __ffsll((long long)kw) - 1;
            kw &= kw - 1;
            int j = base + rr;
            float4 bx = g_box[gb + j];
            size_t o = ((size_t)b * POST + r) * 4;
            obox[o + 0] = bx.x; obox[o + 1] = bx.y;
            obox[o + 2] = bx.z; obox[o + 3] = bx.w;
            oidx[(size_t)b * POST + r] = (float)j;
            oval[(size_t)b * POST + r] = 1.0f;
            r++;
        }
    }
}

// ------------------------------------------------------------------
extern "C" void kernel_launch(void* const* d_in, const int* in_sizes, int n_in,
                              void* d_out, int out_size)
{
    const float* fg  = (const float*)d_in[0];
    const float* reg = (const float*)d_in[1];
    const float* anc = (const float*)d_in[2];
    const int*   ph  = (const int*)d_in[3];
    const int*   pw  = (const int*)d_in[4];

    int B = in_sizes[0] / N_BOX;
    if (B < 1) B = 1;
    if (B > MAX_B) B = MAX_B;

    const int SORT_SMEM = (N_BOX + N_BOX / 16) * (int)sizeof(u64);
    cudaFuncSetAttribute(sort_decode_full_kernel,
                         cudaFuncAttributeMaxDynamicSharedMemorySize, SORT_SMEM);

    // fast path: top-2048 selection + prefix NMS
    select_kernel<<<B, 1024>>>(fg, reg, anc, ph, pw);
    maskgen_kernel_t<256, true><<<dim3(PRE / 256, PRE / 256, B), 256>>>();
    resolve_prefix_kernel<<<B, 256>>>((float*)d_out, B);

    // exact fallback (gated; early-returns when prefix succeeded)
    sort_decode_full_kernel<<<B, TSORT, SORT_SMEM>>>(fg, reg, anc, ph, pw);
    maskgen_kernel_t<1024, false><<<dim3(N_BOX / 256, N_BOX / 1024, B), 256>>>();
    resolve_full_kernel<<<B, NW>>>((float*)d_out, B);
}

// round 7
// speedup vs baseline: 192.1143x; 1.8001x over previous
#include <cuda_runtime.h>
#include <cstdint>

typedef unsigned long long u64;

#define N_BOX   16384
#define TSORT   1024
#define POST    1000
#define NMS_TH  0.7f
#define MAX_B   8
#define NW      256            // 64-bit words per full mask row
#define PRE     2048           // prefix length
#define PNW     (PRE / 64)     // 32 prefix words
#define NSEL    4096           // candidate sort size

#define CBASE 0.4117647058823529f     // 0.7/1.7
#define CHI   (CBASE * 1.02f)
#define CLO   (CBASE * 0.98f)

// Global scratch (allocation-free rule -> __device__ globals)
__device__ float4 g_box [MAX_B * N_BOX];
__device__ float  g_area[MAX_B * N_BOX];
__device__ u64    g_mask[(size_t)MAX_B * N_BOX * NW];
__device__ u64    g_diag[MAX_B * N_BOX];
__device__ u64    g_sum [MAX_B * N_BOX * 4];
__device__ int    g_done  [MAX_B];     // prefix path produced final output
__device__ int    g_sel_ok[MAX_B];     // top-2048 selection succeeded

__device__ __forceinline__ int physi(int i) { return i + (i >> 4); }

__device__ __forceinline__ unsigned score_key(float f)
{
    unsigned u   = __float_as_uint(f);
    unsigned asc = u ^ ((u >> 31) ? 0xFFFFFFFFu : 0x80000000u);
    return ~asc;                       // ascending dsc == descending score
}

__device__ __forceinline__ void decode_store(size_t gb, int j, int i,
                                             const float4* anc4, const float4* reg4,
                                             float maxx, float maxy)
{
    float4 A = anc4[i];
    float4 R = reg4[i];
    float cx = A.z * R.x + A.x;
    float cy = A.w * R.y + A.y;
    float w  = A.z * expf(R.z);
    float h  = A.w * expf(R.w);
    float x1 = fminf(fmaxf(cx - w * 0.5f, 0.f), maxx);
    float x2 = fminf(fmaxf(cx + w * 0.5f, 0.f), maxx);
    float y1 = fminf(fmaxf(cy - h * 0.5f, 0.f), maxy);
    float y2 = fminf(fmaxf(cy + h * 0.5f, 0.f), maxy);
    g_box [gb + j] = make_float4(x1, y1, x2, y2);
    g_area[gb + j] = (x2 - x1) * (y2 - y1);
}

// ------------------------------------------------------------------
// Kernel A: top-2048 selection + sort-4096 + decode (per batch block)
// ------------------------------------------------------------------
__global__ __launch_bounds__(1024, 1)
void select_kernel(const float* __restrict__ fg,
                   const float* __restrict__ reg,
                   const float* __restrict__ anc,
                   const int*   __restrict__ p_h,
                   const int*   __restrict__ p_w)
{
    __shared__ u64      keys[NSEL + NSEL / 16];
    __shared__ unsigned hist[2048];
    __shared__ int      sc  [1024];
    __shared__ int      s_T, s_Clt, s_cnt_lt, s_cnt_eq;

    const int b   = blockIdx.x;
    const int tid = threadIdx.x;
    const size_t gb = (size_t)b * N_BOX;
    const float* fgb = fg + gb;

    hist[tid] = 0u; hist[tid + 1024] = 0u;
    if (tid == 0) { s_cnt_lt = 0; s_cnt_eq = 0; }
    __syncthreads();

    for (int j = tid; j < N_BOX; j += 1024)
        atomicAdd(&hist[score_key(fgb[j]) >> 21], 1u);
    __syncthreads();

    const unsigned h0 = hist[2 * tid], h1 = hist[2 * tid + 1];
    int v = (int)(h0 + h1);
    sc[tid] = v;
    __syncthreads();
    for (int off = 1; off < 1024; off <<= 1) {
        int vv = sc[tid];
        if (tid >= off) vv += sc[tid - off];
        __syncthreads();
        sc[tid] = vv;
        __syncthreads();
    }
    {
        int inc = sc[tid];
        int cb  = inc - v;
        if (cb < PRE && inc >= PRE) {
            if (cb + (int)h0 >= PRE) { s_T = 2 * tid;     s_Clt = cb; }
            else                     { s_T = 2 * tid + 1; s_Clt = cb + (int)h0; }
        }
    }
    __syncthreads();
    const int T = s_T, Clt = s_Clt;
    const int M = Clt + (int)hist[T];
    if (M > NSEL) {
        if (tid == 0) g_sel_ok[b] = 0;
        return;
    }

    const int lane = tid & 31;
    for (int j = tid; j < N_BOX; j += 1024) {
        unsigned dsc = score_key(fgb[j]);
        int bin = (int)(dsc >> 21);
        bool plt = bin < T, peq = bin == T;
        unsigned mlt = __ballot_sync(0xffffffffu, plt);
        unsigned meq = __ballot_sync(0xffffffffu, peq);
        int blt = 0, beq = 0;
        if (lane == 0) {
            if (mlt) blt = atomicAdd(&s_cnt_lt, __popc(mlt));
            if (meq) beq = atomicAdd(&s_cnt_eq, __popc(meq));
        }
        blt = __shfl_sync(0xffffffffu, blt, 0);
        beq = __shfl_sync(0xffffffffu, beq, 0);
        unsigned below = (1u << lane) - 1u;
        u64 key = ((u64)dsc << 32) | (unsigned)j;
        if (plt) keys[physi(blt + __popc(mlt & below))]       = key;
        if (peq) keys[physi(Clt + beq + __popc(meq & below))] = key;
    }
    __syncthreads();
    for (int p = M + tid; p < NSEL; p += 1024) keys[physi(p)] = ~0ull;
    __syncthreads();

    for (int k = 2; k <= NSEL; k <<= 1) {
        for (int jj = k >> 1; jj > 0; jj >>= 1) {
            #pragma unroll
            for (int t = 0; t < 2; t++) {
                int s  = tid + t * 1024;
                int i  = ((s & ~(jj - 1)) << 1) | (s & (jj - 1));
                int j2 = i | jj;
                bool up = ((i & k) == 0);
                int pi = physi(i), pj = physi(j2);
                u64 a = keys[pi], c = keys[pj];
                if ((a > c) == up) { keys[pi] = c; keys[pj] = a; }
            }
            __syncthreads();
        }
    }

    int hv = *p_h, wv = *p_w;
    int H = (hv > 0 && hv < 1000000) ? hv : (int)__int_as_float(hv);
    int W = (wv > 0 && wv < 1000000) ? wv : (int)__int_as_float(wv);
    const float maxy = (float)H - 1.0f;
    const float maxx = (float)W - 1.0f;
    const float4* anc4 = (const float4*)anc + gb;
    const float4* reg4 = (const float4*)reg + gb;
    #pragma unroll
    for (int t = 0; t < 2; t++) {
        int j = tid + t * 1024;
        int i = (int)(unsigned)(keys[physi(j)] & 0xFFFFFFFFull);
        decode_store(gb, j, i, anc4, reg4, maxx, maxy);
    }
    if (tid == 0) g_sel_ok[b] = 1;
}

// ------------------------------------------------------------------
// Kernel B (fallback): full per-batch stable sort + decode (gated)
// ------------------------------------------------------------------
template<int JJ>
__device__ __forceinline__ void reg_stage(u64 v[16], int base, int k)
{
    #pragma unroll
    for (int l = 0; l < 16; l++) if ((l & JJ) == 0) {
        const int p = l | JJ;
        bool up = (((base + l) & k) == 0);
        u64 a = v[l], c = v[p];
        if ((a > c) == up) { v[l] = c; v[p] = a; }
    }
}

__global__ __launch_bounds__(TSORT, 1)
void sort_decode_full_kernel(const float* __restrict__ fg,
                             const float* __restrict__ reg,
                             const float* __restrict__ anc,
                             const int*   __restrict__ p_h,
                             const int*   __restrict__ p_w)
{
    const int b = blockIdx.x;
    if (g_done[b]) return;

    extern __shared__ u64 sk[];
    const int tid = threadIdx.x;
    const size_t gb = (size_t)b * N_BOX;

    int hv = *p_h, wv = *p_w;
    int H = (hv > 0 && hv < 1000000) ? hv : (int)__int_as_float(hv);
    int W = (wv > 0 && wv < 1000000) ? wv : (int)__int_as_float(wv);
    const float maxy = (float)H - 1.0f;
    const float maxx = (float)W - 1.0f;

    const float* fgb = fg + gb;
    for (int j = tid; j < N_BOX; j += TSORT)
        sk[physi(j)] = ((u64)score_key(fgb[j]) << 32) | (unsigned)j;
    __syncthreads();

    const int base = tid * 16;
    u64 v[16];
    #pragma unroll
    for (int l = 0; l < 16; l++) v[l] = sk[physi(base + l)];
    reg_stage<1>(v, base, 2);
    reg_stage<2>(v, base, 4);  reg_stage<1>(v, base, 4);
    reg_stage<4>(v, base, 8);  reg_stage<2>(v, base, 8);  reg_stage<1>(v, base, 8);
    reg_stage<8>(v, base, 16); reg_stage<4>(v, base, 16); reg_stage<2>(v, base, 16); reg_stage<1>(v, base, 16);
    #pragma unroll
    for (int l = 0; l < 16; l++) sk[physi(base + l)] = v[l];
    __syncthreads();

    for (int k = 32; k <= N_BOX; k <<= 1) {
        for (int jj = k >> 1; jj >= 16; jj >>= 1) {
            for (int s = tid; s < N_BOX / 2; s += TSORT) {
                int i  = ((s & ~(jj - 1)) << 1) | (s & (jj - 1));
                int j2 = i | jj;
                bool up = ((i & k) == 0);
                int pi = physi(i), pj = physi(j2);
                u64 a = sk[pi], c = sk[pj];
                if ((a > c) == up) { sk[pi] = c; sk[pj] = a; }
            }
            __syncthreads();
        }
        #pragma unroll
        for (int l = 0; l < 16; l++) v[l] = sk[physi(base + l)];
        reg_stage<8>(v, base, k); reg_stage<4>(v, base, k);
        reg_stage<2>(v, base, k); reg_stage<1>(v, base, k);
        #pragma unroll
        for (int l = 0; l < 16; l++) sk[physi(base + l)] = v[l];
        __syncthreads();
    }

    const float4* anc4 = (const float4*)anc + gb;
    const float4* reg4 = (const float4*)reg + gb;
    for (int j = tid; j < N_BOX; j += TSORT) {
        int i = (int)(unsigned)(sk[physi(j)] & 0xFFFFFFFFull);
        decode_store(gb, j, i, anc4, reg4, maxx, maxy);
    }
}

// ------------------------------------------------------------------
// Kernel C: suppression bitmask generation (templated tile / gate)
// ------------------------------------------------------------------
template<int COLTILE, bool PREFIX_MODE>
__global__ __launch_bounds__(256)
void maskgen_kernel_t()
{
    const int b = blockIdx.z;
    if (PREFIX_MODE) { if (!g_sel_ok[b]) return; }
    else             { if (g_done[b])   return; }

    const int rowbase = blockIdx.x << 8;
    const int colbase = blockIdx.y * COLTILE;
    if (colbase + COLTILE <= rowbase) return;

    __shared__ float4 s_cb[COLTILE];
    __shared__ float2 s_kc[COLTILE];
    __shared__ float  s_ca[COLTILE];
    const int tid = threadIdx.x;
    const size_t gb = (size_t)b * N_BOX;

    for (int t = tid; t < COLTILE; t += 256) {
        float4 cb = g_box [gb + colbase + t];
        float  ca = g_area[gb + colbase + t];
        s_cb[t] = cb;
        s_ca[t] = ca;
        s_kc[t] = make_float2(CHI * ca, CLO * ca);
    }
    __syncthreads();

    const int    i   = rowbase + tid;
    const float4 rb  = g_box [gb + i];
    const float  ra  = g_area[gb + i];
    const float  uhi = CHI * (ra + 1e-9f);
    const float  ulo = CLO * (ra + 1e-9f);
    const int    myw = i >> 6;

    #pragma unroll
    for (int w = 0; w < COLTILE / 64; w++) {
        const int ct = (colbase >> 6) + w;
        if (ct < myw) continue;

        unsigned acc_h[2], unc_h[2];
        #pragma unroll
        for (int h = 0; h < 2; h++) {
            const int cb0 = (w << 6) + (h << 5);
            unsigned acc = 0, unc = 0;
            #pragma unroll 16
            for (int cc = 31; cc >= 0; cc--) {
                float4 cb = s_cb[cb0 + cc];
                float2 kc = s_kc[cb0 + cc];
                float iw = fminf(rb.z, cb.z) - fmaxf(rb.x, cb.x);
                float ih = fminf(rb.w, cb.w) - fmaxf(rb.y, cb.y);
                float inter = fmaxf(iw, 0.f) * fmaxf(ih, 0.f);
                bool hib = inter > (uhi + kc.x);
                bool unb = (!hib) && (inter >= (ulo + kc.y));
                acc = acc * 2u + (hib ? 1u : 0u);
                unc = unc * 2u + (unb ? 1u : 0u);
            }
            acc_h[h] = acc; unc_h[h] = unc;
        }

        u64 bits  = ((u64)acc_h[1] << 32) | acc_h[0];
        u64 unc64 = ((u64)unc_h[1] << 32) | unc_h[0];

        while (unc64) {
            int cc = __ffsll((long long)unc64) - 1; unc64 &= unc64 - 1;
            float4 cb = s_cb[(w << 6) + cc];
            float  ca = s_ca[(w << 6) + cc];
            float iw = fminf(rb.z, cb.z) - fmaxf(rb.x, cb.x);
            float ih = fminf(rb.w, cb.w) - fmaxf(rb.y, cb.y);
            float inter = fmaxf(iw, 0.f) * fmaxf(ih, 0.f);
            float iou = inter / (ra + ca - inter + 1e-9f);
            if (iou > NMS_TH) bits |= 1ull << cc;
        }

        if (ct == myw) {
            int s = (i & 63) + 1;
            u64 m = (s >= 64) ? 0ull : (~0ull << s);
            g_diag[gb + i] = bits & m;
        } else if (bits) {
            g_mask[(gb + i) * NW + ct] = bits;
            atomicOr(&g_sum[((gb + i) << 2) + (ct >> 6)], 1ull << (ct & 63));
        }
    }
}

// ------------------------------------------------------------------
// Kernel D: prefix resolve — sparse serial loop + early stop at 1000 kept
// ------------------------------------------------------------------
__global__ __launch_bounds__(256, 1)
void resolve_prefix_kernel(float* __restrict__ out, int B)
{
    __shared__ u64      sdiag[PRE];          // 16 KB
    __shared__ unsigned ss0  [PRE];          // 8 KB
    __shared__ unsigned s_nz32[64];          // per-32-row nonzero ballots
    __shared__ u64      s_nz [PNW];          // per-chunk nonzero-diag masks
    __shared__ u64      remv [PNW];
    __shared__ u64      keepw[PNW];
    __shared__ u64      s_kept;
    __shared__ int      s_cnt;
    __shared__ int      s_scan[PNW];

    const int b   = blockIdx.x;
    const int tid = threadIdx.x;
    const size_t gb = (size_t)b * N_BOX;

    if (!g_sel_ok[b]) { if (tid == 0) g_done[b] = 0; return; }

    for (int j = tid; j < PRE; j += 256) {
        sdiag[j] = g_diag[gb + j];
        ss0[j]   = (unsigned)g_sum[(gb + j) << 2];
    }
    if (tid < PNW) { remv[tid] = 0ull; keepw[tid] = 0ull; }
    if (tid == 0)  s_cnt = 0;
    __syncthreads();

    // nonzero-diag ballots: warp w covers rows [256w, 256w+256)
    {
        const int lane = tid & 31, w = tid >> 5;
        #pragma unroll
        for (int k = 0; k < 8; k++) {
            int row = (w << 8) + (k << 5) + lane;
            unsigned m = __ballot_sync(0xffffffffu, sdiag[row] != 0ull);
            if (lane == 0) s_nz32[(w << 3) + k] = m;
        }
    }
    __syncthreads();
    if (tid < PNW)
        s_nz[tid] = ((u64)s_nz32[2 * tid + 1] << 32) | s_nz32[2 * tid];
    __syncthreads();

    int chunks_done = PNW;
    for (int c = 0; c < PNW; c++) {
        if (tid == 0) {
            u64 cur = ~remv[c];
            u64 rem = s_nz[c] & cur;
            const u64* d = &sdiag[c << 6];
            while (rem) {
                int r = __ffsll((long long)rem) - 1;
                u64 bit = 1ull << r;
                rem &= rem - 1;
                if (cur & bit) {            // still alive -> kept -> suppress victims
                    u64 dd = d[r];
                    cur &= ~dd;
                    rem &= ~dd;
                }
            }
            keepw[c] = cur;
            s_kept   = cur;
            s_cnt   += __popcll(cur);
        }
        __syncthreads();

        const u64 kb = s_kept;
        if (tid < 64 && ((kb >> tid) & 1ull)) {
            const int row = (c << 6) + tid;
            unsigned s = ss0[row] & ~((c + 1 < 32) ? ((1u << (c + 1)) - 1u) : 0xFFFFFFFFu);
            while (s) {
                int k = __ffs(s) - 1; s &= s - 1;
                atomicOr(&remv[k], g_mask[(gb + row) * NW + k]);
            }
        }
        __syncthreads();

        if (s_cnt >= POST) { chunks_done = c + 1; break; }   // uniform: s_cnt in smem
    }

    const int done = (s_cnt >= POST);
    if (tid == 0) g_done[b] = done;
    if (!done) return;
    (void)chunks_done;

    float* obox = out;
    float* oidx = out + (size_t)B * POST * 4;
    float* oval = oidx + (size_t)B * POST;

    if (tid < 32) {
        int cnt = __popcll(keepw[tid]);
        int scv = cnt;
        #pragma unroll
        for (int off = 1; off < 32; off <<= 1) {
            int t = __shfl_up_sync(0xffffffffu, scv, off);
            if (tid >= off) scv += t;
        }
        s_scan[tid] = scv;
    }
    __syncthreads();

    if (tid < 32) {
        u64 kw = keepw[tid];
        int r = s_scan[tid] - __popcll(kw);
        const int base = tid << 6;
        while (kw && r < POST) {
            int rr = __ffsll((long long)kw) - 1;
            kw &= kw - 1;
            int j = base + rr;
            float4 bx = g_box[gb + j];
            size_t o = ((size_t)b * POST + r) * 4;
            obox[o + 0] = bx.x; obox[o + 1] = bx.y;
            obox[o + 2] = bx.z; obox[o + 3] = bx.w;
            oidx[(size_t)b * POST + r] = (float)j;
            oval[(size_t)b * POST + r] = 1.0f;
            r++;
        }
    }
}

// ------------------------------------------------------------------
// Kernel E: full resolve (fallback only)
// ------------------------------------------------------------------
__global__ __launch_bounds__(NW, 1)
void resolve_full_kernel(float* __restrict__ out, int B)
{
    const int b = blockIdx.x;
    if (g_done[b]) return;

    __shared__ u64 remv [NW];
    __shared__ u64 keepw[NW];
    __shared__ u64 sdiag[2][64];
    __shared__ u64 ssum [2][256];
    __shared__ u64 s_kept;
    __shared__ int s_scan[NW];

    const int tid = threadIdx.x;
    const size_t gb = (size_t)b * N_BOX;

    float* obox = out;
    float* oidx = out + (size_t)B * POST * 4;
    float* oval = oidx + (size_t)B * POST;

    for (int r = tid; r < POST; r += NW) {
        size_t o = ((size_t)b * POST + r) * 4;
        obox[o + 0] = 0.f; obox[o + 1] = 0.f; obox[o + 2] = 0.f; obox[o + 3] = 0.f;
        oidx[(size_t)b * POST + r] = -1.0f;
        oval[(size_t)b * POST + r] = 0.0f;
    }
    remv[tid] = 0ull;

    if (tid < 64) sdiag[0][tid] = g_diag[gb + tid];
    ssum[0][tid] = g_sum[(gb << 2) + tid];
    __syncthreads();

    for (int c = 0; c < NW; c++) {
        const int buf = c & 1, nb = buf ^ 1;
        if (c + 1 < NW) {
            const int nbase = (c + 1) << 6;
            if (tid < 64) sdiag[nb][tid] = g_diag[gb + nbase + tid];
            ssum[nb][tid] = g_sum[((gb + nbase) << 2) + tid];
        }
        if (tid == 0) {
            u64 kept = 0;
            u64 und  = ~remv[c];
            while (und) {
                int r = __ffsll((long long)und) - 1;
                kept |= 1ull << r;
                und &= ~(sdiag[buf][r] | (1ull << r));
            }
            keepw[c] = kept;
            s_kept   = kept;
        }
        __syncthreads();
        const u64 kb = s_kept;
        if (tid < 64 && ((kb >> tid) & 1ull)) {
            const int row = (c << 6) + tid;
            const u64* sp = &ssum[buf][tid << 2];
            #pragma unroll
            for (int j = 0; j < 4; j++) {
                u64 s = sp[j];
                while (s) {
                    int k = (j << 6) + __ffsll((long long)s) - 1;
                    s &= s - 1;
                    atomicOr(&remv[k], g_mask[(gb + row) * NW + k]);
                }
            }
        }
        __syncthreads();
    }

    s_scan[tid] = __popcll(keepw[tid]);
    __syncthreads();
    for (int off = 1; off < NW; off <<= 1) {
        int vv = s_scan[tid];
        if (tid >= off) vv += s_scan[tid - off];
        __syncthreads();
        s_scan[tid] = vv;
        __syncthreads();
    }
    {
        u64 kw = keepw[tid];
        int r = s_scan[tid] - __popcll(kw);
        const int base = tid << 6;
        while (kw && r < POST) {
            int rr = __ffsll((long long)kw) - 1;
            kw &= kw - 1;
            int j = base + rr;
            float4 bx = g_box[gb + j];
            size_t o = ((size_t)b * POST + r) * 4;
            obox[o + 0] = bx.x; obox[o + 1] = bx.y;
            obox[o + 2] = bx.z; obox[o + 3] = bx.w;
            oidx[(size_t)b * POST + r] = (float)j;
            oval[(size_t)b * POST + r] = 1.0f;
            r++;
        }
    }
}

// ------------------------------------------------------------------
extern "C" void kernel_launch(void* const* d_in, const int* in_sizes, int n_in,
                              void* d_out, int out_size)
{
    const float* fg  = (const float*)d_in[0];
    const float* reg = (const float*)d_in[1];
    const float* anc = (const float*)d_in[2];
    const int*   ph  = (const int*)d_in[3];
    const int*   pw  = (const int*)d_in[4];

    int B = in_sizes[0] / N_BOX;
    if (B < 1) B = 1;
    if (B > MAX_B) B = MAX_B;

    const int SORT_SMEM = (N_BOX + N_BOX / 16) * (int)sizeof(u64);
    cudaFuncSetAttribute(sort_decode_full_kernel,
                         cudaFuncAttributeMaxDynamicSharedMemorySize, SORT_SMEM);

    // fast path
    select_kernel<<<B, 1024>>>(fg, reg, anc, ph, pw);
    maskgen_kernel_t<256, true><<<dim3(PRE / 256, PRE / 256, B), 256>>>();
    resolve_prefix_kernel<<<B, 256>>>((float*)d_out, B);

    // exact fallback (gated)
    sort_decode_full_kernel<<<B, TSORT, SORT_SMEM>>>(fg, reg, anc, ph, pw);
    maskgen_kernel_t<1024, false><<<dim3(N_BOX / 256, N_BOX / 1024, B), 256>>>();
    resolve_full_kernel<<<B, NW>>>((float*)d_out, B);
}